// round 12
// baseline (speedup 1.0000x reference)
#include <cuda_runtime.h>
#include <math.h>

#define B_ 32
#define T_ 256
#define S_ 512
#define H_ 512
#define G_ 2048   // 4*H
#define NB 256    // 8 groups x 32 blocks
#define NT 256
#define GSZ 32
#define NGRP 8

// smem floats: [0,16384) Waout slice; [16384,24576) scr; [24576,24640) sml
#define SCR 16384
#define SML 24576
#define SMEM_FLOATS 24640

// ---------------- scratch: __device__ globals ---------------------------------
__device__ float g_XG[T_ * B_ * G_];       // layer0 pre-gated input (64 MB)
__device__ float g_X1[T_ * B_ * H_];       // layer0 outputs (16 MB)
__device__ float g_WhT[2 * G_ * H_];       // Wh transposed [lay][n][k]
__device__ float g_WiT[G_ * H_];           // Wi layer1 transposed [n][k]
__device__ float g_WainT[2 * H_ * H_];     // Wa_in transposed [lay][n][k]
__device__ float g_WaoutT[2 * H_ * 2 * H_];// Wa_out transposed [lay][n][k]
__device__ float g_h[2 * B_ * H_];
__device__ float g_c[2 * B_ * H_];
__device__ float g_cat[2 * B_ * 2 * H_];   // [wc | hy]
__device__ float g_target[2 * B_ * H_];
__device__ float g_pm[2 * B_ * 4];
__device__ float g_pz[2 * B_ * 4];
__device__ float g_pwc[2 * B_ * 4 * H_];
__device__ float g_M[T_ * B_];             // layer1 softmax max
__device__ float g_iZ[T_ * B_];            // layer1 1/Z

// ---------------- sync state ---------------------------------------------------
__device__ unsigned g_gcnt[NGRP];
__device__ unsigned g_ggen[NGRP];
__device__ unsigned g_grst[NGRP];
__device__ unsigned g_bcnt[2 * B_];        // per-(layer,b) minisync (monotonic)
__device__ unsigned g_p0[4];               // layer0 progress per batch octet

__device__ __forceinline__ unsigned atom_add_acqrel(unsigned* p, unsigned v) {
    unsigned old;
    asm volatile("atom.add.acq_rel.gpu.u32 %0, [%1], %2;"
                 : "=r"(old) : "l"(p), "r"(v) : "memory");
    return old;
}
__device__ __forceinline__ unsigned ld_acq(unsigned* p) {
    unsigned v;
    asm volatile("ld.acquire.gpu.u32 %0, [%1];" : "=r"(v) : "l"(p) : "memory");
    return v;
}
__device__ __forceinline__ void st_rel(unsigned* p, unsigned v) {
    asm volatile("st.release.gpu.u32 [%0], %1;" :: "l"(p), "r"(v) : "memory");
}
__device__ __forceinline__ void gbar(int gid, unsigned target) {
    __syncthreads();
    if (threadIdx.x == 0) {
        unsigned old = atom_add_acqrel(&g_gcnt[gid], 1u);
        if (old == GSZ - 1) {
            g_gcnt[gid] = 0;
            st_rel(&g_ggen[gid], target);
        } else {
            while (ld_acq(&g_ggen[gid]) != target) { }
        }
    }
    __syncthreads();
}

// ---------------- tiled matrix transpose: out[n][k] = in[k][n] ----------------
__global__ void __launch_bounds__(256) k_tr(const float* __restrict__ in,
                                            float* __restrict__ out,
                                            int K, int N) {
    __shared__ float tile[32][33];
    const int tx = threadIdx.x & 31, ty = threadIdx.x >> 5;  // 32x8
    const int n0 = blockIdx.x * 32, k0 = blockIdx.y * 32;
    for (int dy = ty; dy < 32; dy += 8)
        tile[dy][tx] = in[(size_t)(k0 + dy) * N + n0 + tx];
    __syncthreads();
    for (int dy = ty; dy < 32; dy += 8)
        out[(size_t)(n0 + dy) * K + k0 + tx] = tile[tx][dy];
}

// ---------------- precompute XG = x @ Wi0 + (bi0 + bh0), layer 0 only ---------
__global__ void __launch_bounds__(256) k_pre(const float* __restrict__ Xin,
                                             const float* __restrict__ Wi,
                                             const float* __restrict__ bi,
                                             const float* __restrict__ bh) {
    __shared__ float As[16][128];
    __shared__ float Bs[16][64];
    const int tid = threadIdx.x;
    const int tx = tid & 15, ty = tid >> 4;
    const int n0 = blockIdx.x * 64, m0 = blockIdx.y * 128;
    const int m_l = tid & 127, kb = (tid >> 7) * 8;
    const int m = m0 + m_l;
    const int bb = m & 31, tt = m >> 5;
    const float* arow = Xin + ((size_t)bb * T_ + tt) * H_;
    const int bkk = tid >> 4, bnn = (tid & 15) * 4;

    float acc[8][4];
#pragma unroll
    for (int i = 0; i < 8; i++)
#pragma unroll
        for (int j = 0; j < 4; j++) acc[i][j] = 0.f;

    for (int k0 = 0; k0 < H_; k0 += 16) {
        float4 a0 = *(const float4*)(arow + k0 + kb);
        float4 a1 = *(const float4*)(arow + k0 + kb + 4);
        As[kb + 0][m_l] = a0.x; As[kb + 1][m_l] = a0.y;
        As[kb + 2][m_l] = a0.z; As[kb + 3][m_l] = a0.w;
        As[kb + 4][m_l] = a1.x; As[kb + 5][m_l] = a1.y;
        As[kb + 6][m_l] = a1.z; As[kb + 7][m_l] = a1.w;
        *(float4*)&Bs[bkk][bnn] =
            *(const float4*)(Wi + (size_t)(k0 + bkk) * G_ + n0 + bnn);
        __syncthreads();
#pragma unroll
        for (int kk = 0; kk < 16; kk++) {
            float4 b4  = *(const float4*)&Bs[kk][tx * 4];
            float4 alo = *(const float4*)&As[kk][ty * 8];
            float4 ahi = *(const float4*)&As[kk][ty * 8 + 4];
            float av[8] = {alo.x, alo.y, alo.z, alo.w, ahi.x, ahi.y, ahi.z, ahi.w};
#pragma unroll
            for (int i = 0; i < 8; i++) {
                acc[i][0] = fmaf(av[i], b4.x, acc[i][0]);
                acc[i][1] = fmaf(av[i], b4.y, acc[i][1]);
                acc[i][2] = fmaf(av[i], b4.z, acc[i][2]);
                acc[i][3] = fmaf(av[i], b4.w, acc[i][3]);
            }
        }
        __syncthreads();
    }
    float4 b1 = *(const float4*)(bi + n0 + tx * 4);
    float4 b2 = *(const float4*)(bh + n0 + tx * 4);
    float4 bias = {b1.x + b2.x, b1.y + b2.y, b1.z + b2.z, b1.w + b2.w};
#pragma unroll
    for (int i = 0; i < 8; i++) {
        float4 o = {acc[i][0] + bias.x, acc[i][1] + bias.y,
                    acc[i][2] + bias.z, acc[i][3] + bias.w};
        *(float4*)&g_XG[(size_t)(m0 + ty * 8 + i) * G_ + n0 + tx * 4] = o;
    }
}

// ---------------- persistent wavefront kernel: both layers concurrently -------
__global__ void __launch_bounds__(NT, 2) k_wave(
    const float* __restrict__ ctx,
    const float* __restrict__ bi,
    const float* __restrict__ bh,
    const float* __restrict__ h0,
    const float* __restrict__ c0,
    float* __restrict__ outx,
    float* __restrict__ outh,
    float* __restrict__ outc,
    float* __restrict__ outa)
{
    extern __shared__ float sm[];
    float* smO = sm;            // Waout slice, float4 index kk*16+nl
    float* scr = sm + SCR;      // 8192-float stage/reduce overlay
    float* sml = sm + SML;      // 64-float small area
    const int blk = blockIdx.x, tid = threadIdx.x;
    const int lane = tid & 31, wrp = tid >> 5;
    const int gid = blk >> 5, gblk = blk & 31;
    const int lay = gid >> 2, oct = gid & 3;
    const int b0g = oct * 8;

    const int bC = b0g + (gblk >> 2), qC = gblk & 3;   // phase C/D mapping
    const int j0A = gblk * 16;                         // phase A j-slice
    const int n0E = gblk * 16;                         // phase B/E n-slice

    const float* biL = bi + lay * G_;
    const float* bhL = bh + lay * G_;

    float* hL   = g_h   + lay * B_ * H_;
    float* cL   = g_c   + lay * B_ * H_;
    float* catL = g_cat + lay * B_ * 2 * H_;
    float* tgtL = g_target + lay * B_ * H_;
    float* pmL  = g_pm  + lay * B_ * 4;
    float* pzL  = g_pz  + lay * B_ * 4;
    float* pwcL = g_pwc + (size_t)lay * B_ * 4 * H_;

    // ---- one-time Waout slice preload (from transposed, float4) ----
    for (int idx = tid; idx < 4096; idx += NT) {
        int kk = idx >> 4, nl = idx & 15;        // kk in [0,256): 4k each
        float4 v = *(const float4*)(g_WaoutT +
            ((size_t)lay * H_ + n0E + nl) * (2 * H_) + kk * 4);
        ((float4*)smO)[kk * 16 + nl] = v;
    }
    __syncthreads();

    for (int t = 0; t < T_; t++) {
        const unsigned t4 = (unsigned)t * 4;

        // ===== cross-layer gate: layer1 step t needs layer0's X1[t] =====
        if (lay == 1) {
            if (tid == 0) {
                unsigned tgt = (unsigned)(t + 1);
                while (ld_acq(&g_p0[oct]) < tgt) { }
            }
            __syncthreads();
        }

        // ===== A: gates, fused LSTM elementwise =====
        {
            const float* hp = (t == 0) ? (h0) : hL;
            if (lay == 0) {
                for (int i = tid; i < 1024; i += NT)
                    ((float4*)scr)[i] = ((const float4*)(hp + b0g * H_))[i];
            } else {
                const float4* xsrc = (const float4*)(g_X1 + ((size_t)t * B_ + b0g) * H_);
                for (int i = tid; i < 1024; i += NT)
                    ((float4*)scr)[i] = xsrc[i];
                for (int i = tid; i < 1024; i += NT)
                    ((float4*)(scr + 4096))[i] = ((const float4*)(hp + b0g * H_))[i];
            }
            __syncthreads();
            const int n_loc = tid & 63;
            const int ks = tid >> 6;                   // 4 k-splits
            const int n = (n_loc >> 4) * H_ + j0A + (n_loc & 15);
            float acc[8];
#pragma unroll
            for (int i = 0; i < 8; i++) acc[i] = 0.f;
            if (lay == 0) {
                const float4* w4 = (const float4*)(g_WhT + (size_t)n * H_ + ks * 128);
                const float* hb = scr + ks * 128;
#pragma unroll 8
                for (int k4 = 0; k4 < 32; k4++) {
                    float4 w = w4[k4];
#pragma unroll
                    for (int b = 0; b < 8; b++) {
                        float4 h4 = ((const float4*)(hb + b * 512))[k4];
                        acc[b] = fmaf(h4.x, w.x, fmaf(h4.y, w.y,
                                 fmaf(h4.z, w.z, fmaf(h4.w, w.w, acc[b]))));
                    }
                }
            } else {
                const float4* w4;
                const float* hb;
                if (ks < 2) {
                    w4 = (const float4*)(g_WiT + (size_t)n * H_ + ks * 256);
                    hb = scr + ks * 256;
                } else {
                    w4 = (const float4*)(g_WhT + ((size_t)G_ + n) * H_ + (ks - 2) * 256);
                    hb = scr + 4096 + (ks - 2) * 256;
                }
#pragma unroll 8
                for (int k4 = 0; k4 < 64; k4++) {
                    float4 w = w4[k4];
#pragma unroll
                    for (int b = 0; b < 8; b++) {
                        float4 h4 = ((const float4*)(hb + b * 512))[k4];
                        acc[b] = fmaf(h4.x, w.x, fmaf(h4.y, w.y,
                                 fmaf(h4.z, w.z, fmaf(h4.w, w.w, acc[b]))));
                    }
                }
            }
            __syncthreads();                           // staging reads done
#pragma unroll
            for (int b = 0; b < 8; b++) scr[(ks * 64 + n_loc) * 8 + b] = acc[b];
            __syncthreads();
            for (int slot = tid; slot < 512; slot += NT) {
                int bb = slot >> 6, nl = slot & 63;
                int g2 = nl >> 4, j2 = nl & 15;
                float v = scr[nl * 8 + bb] + scr[(64 + nl) * 8 + bb]
                        + scr[(128 + nl) * 8 + bb] + scr[(192 + nl) * 8 + bb];
                if (lay == 0)
                    v += g_XG[(size_t)(t * B_ + b0g + bb) * G_ + g2 * H_ + j0A + j2];
                else
                    v += biL[g2 * H_ + j0A + j2] + bhL[g2 * H_ + j0A + j2];
                scr[4096 + slot] = v;
            }
            __syncthreads();
            if (tid < 128) {
                int bb = tid >> 4, j2 = tid & 15;
                float gi = scr[4096 + bb * 64 + j2];
                float gf = scr[4096 + bb * 64 + 16 + j2];
                float gg = scr[4096 + bb * 64 + 32 + j2];
                float go = scr[4096 + bb * 64 + 48 + j2];
                int b = b0g + bb, j = j0A + j2;
                float cold = (t == 0) ? c0[b * H_ + j] : cL[b * H_ + j];
                float ig = 1.f / (1.f + expf(-gi));
                float fg = 1.f / (1.f + expf(-gf));
                float g2v = tanhf(gg);
                float og = 1.f / (1.f + expf(-go));
                float cy = fg * cold + ig * g2v;
                float hy = og * tanhf(cy);
                cL[b * H_ + j] = cy;
                catL[b * 2 * H_ + H_ + j] = hy;
            }
        }
        gbar(gid, t4 + 1);

        // ===== B: target = hy @ Wa_in (transposed weights) =====
        {
            for (int i = tid; i < 1024; i += NT) {
                int bb = i >> 7, f = i & 127;
                ((float4*)scr)[i] = ((const float4*)(catL + (b0g + bb) * 1024 + 512))[f];
            }
            __syncthreads();
            const int n_loc = tid & 15, ks = tid >> 4;  // 16 splits x 32 k
            float acc[8];
#pragma unroll
            for (int i = 0; i < 8; i++) acc[i] = 0.f;
            const float4* w4 = (const float4*)(g_WainT +
                ((size_t)lay * H_ + n0E + n_loc) * H_ + ks * 32);
            const float* hb = scr + ks * 32;
#pragma unroll
            for (int k4 = 0; k4 < 8; k4++) {
                float4 w = w4[k4];
#pragma unroll
                for (int b = 0; b < 8; b++) {
                    float4 h4 = ((const float4*)(hb + b * 512))[k4];
                    acc[b] = fmaf(h4.x, w.x, fmaf(h4.y, w.y,
                             fmaf(h4.z, w.z, fmaf(h4.w, w.w, acc[b]))));
                }
            }
            __syncthreads();                           // staging reads done
#pragma unroll
            for (int b = 0; b < 8; b++) scr[(ks * 16 + n_loc) * 8 + b] = acc[b];
            __syncthreads();
            if (tid < 128) {
                int bb = tid >> 4, nn = tid & 15;
                float v = 0.f;
#pragma unroll
                for (int s2 = 0; s2 < 16; s2++) v += scr[(s2 * 16 + nn) * 8 + bb];
                tgtL[(b0g + bb) * H_ + n0E + nn] = v;
            }
        }
        gbar(gid, t4 + 2);

        // ===== C: attention — online softmax, 16 s-rows per warp =====
        {
            const int b = bC, q = qC;
            const int sbase = q * 128;
            const float4* tp = (const float4*)(tgtL + b * H_);
            float4 tg0 = tp[lane],      tg1 = tp[32 + lane];
            float4 tg2 = tp[64 + lane], tg3 = tp[96 + lane];
            float m = -3.4e38f, z = 0.f;
            float4 a0 = {0,0,0,0}, a1 = a0, a2 = a0, a3 = a0;
#pragma unroll 4
            for (int i = 0; i < 16; i++) {
                int s = sbase + wrp * 16 + i;
                const float4* cr = (const float4*)(ctx + ((size_t)s * B_ + b) * H_);
                float4 c0v = cr[lane],      c1v = cr[32 + lane];
                float4 c2v = cr[64 + lane], c3v = cr[96 + lane];
                float p = c0v.x * tg0.x + c0v.y * tg0.y + c0v.z * tg0.z + c0v.w * tg0.w
                        + c1v.x * tg1.x + c1v.y * tg1.y + c1v.z * tg1.z + c1v.w * tg1.w
                        + c2v.x * tg2.x + c2v.y * tg2.y + c2v.z * tg2.z + c2v.w * tg2.w
                        + c3v.x * tg3.x + c3v.y * tg3.y + c3v.z * tg3.z + c3v.w * tg3.w;
#pragma unroll
                for (int o = 16; o; o >>= 1) p += __shfl_xor_sync(0xffffffffu, p, o);
                if (!lane && lay == 1)
                    outa[(size_t)s * (T_ * B_) + t * B_ + b] = p;   // raw score
                float mn = fmaxf(m, p);
                float sc = expf(m - mn);
                float e  = expf(p - mn);
                z = z * sc + e;
                a0.x = a0.x * sc + e * c0v.x; a0.y = a0.y * sc + e * c0v.y;
                a0.z = a0.z * sc + e * c0v.z; a0.w = a0.w * sc + e * c0v.w;
                a1.x = a1.x * sc + e * c1v.x; a1.y = a1.y * sc + e * c1v.y;
                a1.z = a1.z * sc + e * c1v.z; a1.w = a1.w * sc + e * c1v.w;
                a2.x = a2.x * sc + e * c2v.x; a2.y = a2.y * sc + e * c2v.y;
                a2.z = a2.z * sc + e * c2v.z; a2.w = a2.w * sc + e * c2v.w;
                a3.x = a3.x * sc + e * c3v.x; a3.y = a3.y * sc + e * c3v.y;
                a3.z = a3.z * sc + e * c3v.z; a3.w = a3.w * sc + e * c3v.w;
                m = mn;
            }
            if (!lane) { sml[wrp] = m; sml[8 + wrp] = z; }
            __syncthreads();
            if (wrp == 0) {
                float mw = (lane < 8) ? sml[lane] : -3.4e38f;
                float zw = (lane < 8) ? sml[8 + lane] : 0.f;
                float M = mw;
#pragma unroll
                for (int o = 16; o; o >>= 1)
                    M = fmaxf(M, __shfl_xor_sync(0xffffffffu, M, o));
                float cw = expf(mw - M);
                float Zb = zw * cw;
#pragma unroll
                for (int o = 16; o; o >>= 1) Zb += __shfl_xor_sync(0xffffffffu, Zb, o);
                if (lane < 8) sml[16 + lane] = cw;
                if (!lane) { pmL[b * 4 + q] = M; pzL[b * 4 + q] = Zb; }
            }
            __syncthreads();
            float cw = sml[16 + wrp];
            float4* wp4 = (float4*)(scr + wrp * 512);
            float4 s0v = {a0.x*cw, a0.y*cw, a0.z*cw, a0.w*cw};
            float4 s1v = {a1.x*cw, a1.y*cw, a1.z*cw, a1.w*cw};
            float4 s2v = {a2.x*cw, a2.y*cw, a2.z*cw, a2.w*cw};
            float4 s3v = {a3.x*cw, a3.y*cw, a3.z*cw, a3.w*cw};
            wp4[lane] = s0v; wp4[32 + lane] = s1v;
            wp4[64 + lane] = s2v; wp4[96 + lane] = s3v;
            __syncthreads();
            for (int i = tid; i < 512; i += NT) {
                float v = 0.f;
#pragma unroll
                for (int w2 = 0; w2 < 8; w2++) v += scr[w2 * 512 + i];
                pwcL[((size_t)b * 4 + q) * H_ + i] = v;
            }
            __syncthreads();
            if (tid == 0) atom_add_acqrel(&g_bcnt[lay * B_ + b], 1u);
        }

        // ===== D: wait 4 partials of (lay,b), combine -> wc =====
        {
            const int b = bC, q = qC;
            const int k0 = q * 128;
            if (tid == 0) {
                unsigned tgt = 4u * (unsigned)(t + 1);
                while (ld_acq(&g_bcnt[lay * B_ + b]) < tgt) { }
            }
            __syncthreads();
            if (wrp == 0) {
                float M4 = (lane < 4) ? pmL[b * 4 + lane] : -3.4e38f;
                float Z4 = (lane < 4) ? pzL[b * 4 + lane] : 0.f;
                float M = M4;
#pragma unroll
                for (int o = 16; o; o >>= 1)
                    M = fmaxf(M, __shfl_xor_sync(0xffffffffu, M, o));
                float cc = expf(M4 - M);
                float Z = Z4 * cc;
#pragma unroll
                for (int o = 16; o; o >>= 1) Z += __shfl_xor_sync(0xffffffffu, Z, o);
                if (lane < 4) sml[lane] = cc;
                if (!lane) {
                    sml[4] = 1.f / Z;
                    if (lay == 1) { g_M[t * B_ + b] = M; g_iZ[t * B_ + b] = 1.f / Z; }
                }
            }
            __syncthreads();
            if (tid < 128) {
                int k = k0 + tid;
                float iZ = sml[4];
                float v = 0.f;
#pragma unroll
                for (int c2 = 0; c2 < 4; c2++)
                    v += sml[c2] * pwcL[((size_t)b * 4 + c2) * H_ + k];
                catL[b * 2 * H_ + k] = v * iZ;
            }
        }
        gbar(gid, t4 + 3);

        // ===== E: h = tanh([wc|hy] @ Wa_out) (smem weights), outputs =====
        {
            for (int i = tid; i < 2048; i += NT)
                ((float4*)scr)[i] = ((const float4*)(catL + b0g * 1024))[i];
            __syncthreads();
            const int n_loc = tid & 15, ks = tid >> 4;  // 16 splits x 64 k
            float acc[8];
#pragma unroll
            for (int i = 0; i < 8; i++) acc[i] = 0.f;
            const float4* w4p = (const float4*)smO + n_loc;
#pragma unroll 4
            for (int k4 = 0; k4 < 16; k4++) {
                float4 w4 = w4p[(ks * 16 + k4) * 16];
#pragma unroll
                for (int b = 0; b < 8; b++) {
                    float4 h4 = ((const float4*)(scr + b * 1024))[ks * 16 + k4];
                    acc[b] = fmaf(h4.x, w4.x, fmaf(h4.y, w4.y,
                             fmaf(h4.z, w4.z, fmaf(h4.w, w4.w, acc[b]))));
                }
            }
            __syncthreads();                           // staging reads done
#pragma unroll
            for (int b = 0; b < 8; b++) scr[(ks * 16 + n_loc) * 8 + b] = acc[b];
            __syncthreads();
            if (tid < 128) {
                int bb = tid >> 4, nn = tid & 15;
                float v = 0.f;
#pragma unroll
                for (int s2 = 0; s2 < 16; s2++) v += scr[(s2 * 16 + nn) * 8 + bb];
                v = tanhf(v);
                int b = b0g + bb, n = n0E + nn;
                hL[b * H_ + n] = v;
                if (lay == 0)
                    g_X1[((size_t)t * B_ + b) * H_ + n] = v;
                else
                    outx[(size_t)b * (T_ * H_) + (size_t)t * H_ + n] = v;
                if (t == T_ - 1) {
                    outh[lay * B_ * H_ + b * H_ + n] = v;
                    outc[lay * B_ * H_ + b * H_ + n] = cL[b * H_ + n];
                }
            }
        }
        gbar(gid, t4 + 4);

        // layer0 publishes progress for layer1's consumer gate
        if (lay == 0 && gblk == 0 && tid == 0)
            st_rel(&g_p0[oct], (unsigned)(t + 1));
    }

    // reset sync state for next launch
    if (tid == 0) {
        unsigned old = atom_add_acqrel(&g_grst[gid], 1u);
        if (old == GSZ - 1) {
            g_grst[gid] = 0;
#pragma unroll
            for (int i = 0; i < 8; i++) g_bcnt[lay * B_ + b0g + i] = 0;
            if (lay == 1) st_rel(&g_p0[oct], 0u);
            st_rel(&g_ggen[gid], 0u);
        }
    }
}

// ---------------- finalize attention output: normalize raw scores -------------
__global__ void __launch_bounds__(256) k_att(float* __restrict__ outa) {
    const int s = blockIdx.x;
    for (int i = threadIdx.x; i < T_ * B_; i += 256) {
        float v = outa[(size_t)s * (T_ * B_) + i];
        outa[(size_t)s * (T_ * B_) + i] = expf(v - g_M[i]) * g_iZ[i];
    }
}

// ---------------- host orchestration ------------------------------------------
extern "C" void kernel_launch(void* const* d_in, const int* in_sizes, int n_in,
                              void* d_out, int out_size) {
    const float* input = (const float*)d_in[0];
    const float* h0    = (const float*)d_in[1];
    const float* c0    = (const float*)d_in[2];
    const float* ctx   = (const float*)d_in[3];
    const float* Wi    = (const float*)d_in[4];
    const float* bi    = (const float*)d_in[5];
    const float* Wh    = (const float*)d_in[6];
    const float* bh    = (const float*)d_in[7];
    const float* Wain  = (const float*)d_in[8];
    const float* Waout = (const float*)d_in[9];

    float* out  = (float*)d_out;
    float* outx = out;                                   // (B,T,H)
    float* outh = out  + (size_t)B_ * T_ * H_;           // (2,B,H)
    float* outc = outh + 2 * B_ * H_;                    // (2,B,H)
    float* outa = outc + 2 * B_ * H_;                    // (S, T*B)

    // device pointers of transposed-weight buffers
    float *dWhT, *dWiT, *dWainT, *dWaoutT;
    cudaGetSymbolAddress((void**)&dWhT,    g_WhT);
    cudaGetSymbolAddress((void**)&dWiT,    g_WiT);
    cudaGetSymbolAddress((void**)&dWainT,  g_WainT);
    cudaGetSymbolAddress((void**)&dWaoutT, g_WaoutT);

    // one-time transposes (run each call; deterministic, tiny)
    k_tr<<<dim3(G_ / 32, H_ / 32), 256>>>(Wh,            dWhT,            H_, G_);
    k_tr<<<dim3(G_ / 32, H_ / 32), 256>>>(Wh + (size_t)H_ * G_,
                                          dWhT + (size_t)G_ * H_,         H_, G_);
    k_tr<<<dim3(G_ / 32, H_ / 32), 256>>>(Wi + (size_t)H_ * G_, dWiT,     H_, G_);
    k_tr<<<dim3(H_ / 32, H_ / 32), 256>>>(Wain,          dWainT,          H_, H_);
    k_tr<<<dim3(H_ / 32, H_ / 32), 256>>>(Wain + (size_t)H_ * H_,
                                          dWainT + (size_t)H_ * H_,       H_, H_);
    k_tr<<<dim3(H_ / 32, (2 * H_) / 32), 256>>>(Waout,   dWaoutT,     2 * H_, H_);
    k_tr<<<dim3(H_ / 32, (2 * H_) / 32), 256>>>(Waout + (size_t)2 * H_ * H_,
                                          dWaoutT + (size_t)H_ * 2 * H_, 2 * H_, H_);

    const int SMEM = SMEM_FLOATS * 4;  // 98,560 B -> 2 blocks/SM
    cudaFuncSetAttribute(k_wave, cudaFuncAttributeMaxDynamicSharedMemorySize, SMEM);

    k_pre<<<dim3(G_ / 64, (T_ * B_) / 128), 256>>>(input, Wi, bi, bh);
    k_wave<<<NB, NT, SMEM>>>(ctx, bi, bh, h0, c0, outx, outh, outc, outa);
    k_att<<<S_, 256>>>(outa);
}

// round 13
// speedup vs baseline: 1.0868x; 1.0868x over previous
#include <cuda_runtime.h>
#include <math.h>

#define B_ 32
#define T_ 256
#define S_ 512
#define H_ 512
#define G_ 2048   // 4*H
#define NB 256    // 8 groups x 32 blocks
#define NT 256
#define GSZ 32
#define NGRP 8

// smem floats: [0,16384) Waout slice; [16384,24576) scr; [24576,24640) sml
#define SCR 16384
#define SML 24576
#define SMEM_FLOATS 24640

typedef unsigned long long ull;

// ---------------- f32x2 packed-math helpers (sm_100+ PTX) ---------------------
__device__ __forceinline__ ull pk2(float x) {
    ull r; unsigned u = __float_as_uint(x);
    asm("mov.b64 %0, {%1, %1};" : "=l"(r) : "r"(u));
    return r;
}
__device__ __forceinline__ ull fma2(ull a, ull b, ull c) {
    ull d; asm("fma.rn.f32x2 %0, %1, %2, %3;" : "=l"(d) : "l"(a), "l"(b), "l"(c));
    return d;
}
__device__ __forceinline__ ull mul2(ull a, ull b) {
    ull d; asm("mul.rn.f32x2 %0, %1, %2;" : "=l"(d) : "l"(a), "l"(b));
    return d;
}
__device__ __forceinline__ float sum2(ull v) {
    unsigned lo, hi;
    asm("mov.b64 {%0, %1}, %2;" : "=r"(lo), "=r"(hi) : "l"(v));
    return __uint_as_float(lo) + __uint_as_float(hi);
}

// ---------------- scratch: __device__ globals ---------------------------------
__device__ float g_XG[T_ * B_ * G_];       // layer0 pre-gated input (64 MB)
__device__ float g_X1[T_ * B_ * H_];       // layer0 outputs (16 MB)
__device__ float g_h[2 * B_ * H_];
__device__ float g_c[2 * B_ * H_];
__device__ float g_cat[2 * B_ * 2 * H_];   // [wc | hy]
__device__ float g_target[2 * B_ * H_];
__device__ float g_pm[2 * B_ * 4];
__device__ float g_pz[2 * B_ * 4];
__device__ float g_pwc[2 * B_ * 4 * H_];
__device__ float g_M[T_ * B_];             // layer1 softmax max
__device__ float g_iZ[T_ * B_];            // layer1 1/Z

// ---------------- sync state ---------------------------------------------------
__device__ unsigned g_gcnt[NGRP];
__device__ unsigned g_ggen[NGRP];
__device__ unsigned g_grst[NGRP];
__device__ unsigned g_bcnt[2 * B_];        // per-(layer,b) minisync (monotonic)
__device__ unsigned g_p0[4];               // layer0 progress per batch octet

__device__ __forceinline__ unsigned atom_add_acqrel(unsigned* p, unsigned v) {
    unsigned old;
    asm volatile("atom.add.acq_rel.gpu.u32 %0, [%1], %2;"
                 : "=r"(old) : "l"(p), "r"(v) : "memory");
    return old;
}
__device__ __forceinline__ unsigned ld_acq(unsigned* p) {
    unsigned v;
    asm volatile("ld.acquire.gpu.u32 %0, [%1];" : "=r"(v) : "l"(p) : "memory");
    return v;
}
__device__ __forceinline__ void st_rel(unsigned* p, unsigned v) {
    asm volatile("st.release.gpu.u32 [%0], %1;" :: "l"(p), "r"(v) : "memory");
}
__device__ __forceinline__ void gbar(int gid, unsigned target) {
    __syncthreads();
    if (threadIdx.x == 0) {
        unsigned old = atom_add_acqrel(&g_gcnt[gid], 1u);
        if (old == GSZ - 1) {
            g_gcnt[gid] = 0;
            st_rel(&g_ggen[gid], target);
        } else {
            while (ld_acq(&g_ggen[gid]) != target) { }
        }
    }
    __syncthreads();
}

// ---------------- precompute XG = x @ Wi0 + (bi0 + bh0), layer 0 only ---------
__global__ void __launch_bounds__(256) k_pre(const float* __restrict__ Xin,
                                             const float* __restrict__ Wi,
                                             const float* __restrict__ bi,
                                             const float* __restrict__ bh) {
    __shared__ float As[16][128];
    __shared__ float Bs[16][64];
    const int tid = threadIdx.x;
    const int tx = tid & 15, ty = tid >> 4;
    const int n0 = blockIdx.x * 64, m0 = blockIdx.y * 128;
    const int m_l = tid & 127, kb = (tid >> 7) * 8;
    const int m = m0 + m_l;
    const int bb = m & 31, tt = m >> 5;
    const float* arow = Xin + ((size_t)bb * T_ + tt) * H_;
    const int bkk = tid >> 4, bnn = (tid & 15) * 4;

    float acc[8][4];
#pragma unroll
    for (int i = 0; i < 8; i++)
#pragma unroll
        for (int j = 0; j < 4; j++) acc[i][j] = 0.f;

    for (int k0 = 0; k0 < H_; k0 += 16) {
        float4 a0 = *(const float4*)(arow + k0 + kb);
        float4 a1 = *(const float4*)(arow + k0 + kb + 4);
        As[kb + 0][m_l] = a0.x; As[kb + 1][m_l] = a0.y;
        As[kb + 2][m_l] = a0.z; As[kb + 3][m_l] = a0.w;
        As[kb + 4][m_l] = a1.x; As[kb + 5][m_l] = a1.y;
        As[kb + 6][m_l] = a1.z; As[kb + 7][m_l] = a1.w;
        *(float4*)&Bs[bkk][bnn] =
            *(const float4*)(Wi + (size_t)(k0 + bkk) * G_ + n0 + bnn);
        __syncthreads();
#pragma unroll
        for (int kk = 0; kk < 16; kk++) {
            float4 b4  = *(const float4*)&Bs[kk][tx * 4];
            float4 alo = *(const float4*)&As[kk][ty * 8];
            float4 ahi = *(const float4*)&As[kk][ty * 8 + 4];
            float av[8] = {alo.x, alo.y, alo.z, alo.w, ahi.x, ahi.y, ahi.z, ahi.w};
#pragma unroll
            for (int i = 0; i < 8; i++) {
                acc[i][0] = fmaf(av[i], b4.x, acc[i][0]);
                acc[i][1] = fmaf(av[i], b4.y, acc[i][1]);
                acc[i][2] = fmaf(av[i], b4.z, acc[i][2]);
                acc[i][3] = fmaf(av[i], b4.w, acc[i][3]);
            }
        }
        __syncthreads();
    }
    float4 b1 = *(const float4*)(bi + n0 + tx * 4);
    float4 b2 = *(const float4*)(bh + n0 + tx * 4);
    float4 bias = {b1.x + b2.x, b1.y + b2.y, b1.z + b2.z, b1.w + b2.w};
#pragma unroll
    for (int i = 0; i < 8; i++) {
        float4 o = {acc[i][0] + bias.x, acc[i][1] + bias.y,
                    acc[i][2] + bias.z, acc[i][3] + bias.w};
        *(float4*)&g_XG[(size_t)(m0 + ty * 8 + i) * G_ + n0 + tx * 4] = o;
    }
}

// ---------------- persistent wavefront kernel: both layers concurrently -------
__global__ void __launch_bounds__(NT, 2) k_wave(
    const float* __restrict__ ctx,
    const float* __restrict__ Wi,
    const float* __restrict__ bi,
    const float* __restrict__ Wh,
    const float* __restrict__ bh,
    const float* __restrict__ Wain,
    const float* __restrict__ Waout,
    const float* __restrict__ h0,
    const float* __restrict__ c0,
    float* __restrict__ outx,
    float* __restrict__ outh,
    float* __restrict__ outc,
    float* __restrict__ outa)
{
    extern __shared__ float sm[];
    float* smO = sm;            // Waout slice, float4 index kk*16+nl
    float* scr = sm + SCR;      // 8192-float stage/reduce overlay
    float* sml = sm + SML;      // 64-float small area
    const int blk = blockIdx.x, tid = threadIdx.x;
    const int lane = tid & 31, wrp = tid >> 5;
    const int gid = blk >> 5, gblk = blk & 31;
    const int lay = gid >> 2, oct = gid & 3;
    const int b0g = oct * 8;

    const int bC = b0g + (gblk >> 2), qC = gblk & 3;   // phase C/D mapping
    const int j0A = gblk * 16;                         // phase A j-slice
    const int n0E = gblk * 16;                         // phase B/E n-slice

    // per-layer weight pointers
    const float* WiL    = Wi    + (size_t)lay * H_ * G_;
    const float* biL    = bi    + lay * G_;
    const float* WhL    = Wh    + (size_t)lay * H_ * G_;
    const float* bhL    = bh    + lay * G_;
    const float* WainL  = Wain  + (size_t)lay * H_ * H_;
    const float* WaoutL = Waout + (size_t)lay * 2 * H_ * H_;

    float* hL   = g_h   + lay * B_ * H_;
    float* cL   = g_c   + lay * B_ * H_;
    float* catL = g_cat + lay * B_ * 2 * H_;
    float* tgtL = g_target + lay * B_ * H_;
    float* pmL  = g_pm  + lay * B_ * 4;
    float* pzL  = g_pz  + lay * B_ * 4;
    float* pwcL = g_pwc + (size_t)lay * B_ * 4 * H_;

    // ---- one-time Waout slice preload ----
    for (int idx = tid; idx < 16384; idx += NT) {
        int k = idx >> 4, nl = idx & 15;
        smO[((k >> 2) * 16 + nl) * 4 + (k & 3)] =
            WaoutL[(size_t)k * H_ + n0E + nl];
    }
    __syncthreads();

    for (int t = 0; t < T_; t++) {
        const unsigned t4 = (unsigned)t * 4;

        // ===== cross-layer gate: layer1 step t needs layer0's X1[t] =====
        if (lay == 1) {
            if (tid == 0) {
                unsigned tgt = (unsigned)(t + 1);
                while (ld_acq(&g_p0[oct]) < tgt) { }
            }
            __syncthreads();
        }

        // ===== A: gates (packed f32x2), fused LSTM elementwise =====
        {
            const float* hp = (t == 0) ? (h0) : hL;
            if (lay == 0) {
                // stage hT[k][8b]
                for (int i = tid; i < 1024; i += NT) {
                    int b = i & 7, kg = i >> 3;
                    float4 v = *(const float4*)(hp + (b0g + b) * H_ + kg * 4);
                    scr[(kg * 4 + 0) * 8 + b] = v.x;
                    scr[(kg * 4 + 1) * 8 + b] = v.y;
                    scr[(kg * 4 + 2) * 8 + b] = v.z;
                    scr[(kg * 4 + 3) * 8 + b] = v.w;
                }
            } else {
                // stage xT (scr[0..4095]) + hT (scr[4096..8191])
                for (int i = tid; i < 2048; i += NT) {
                    int buf = i >> 10, ii = i & 1023, b = ii & 7, kg = ii >> 3;
                    const float* src = buf ? (hp + (b0g + b) * H_)
                                           : (g_X1 + ((size_t)t * B_ + b0g + b) * H_);
                    float4 v = *(const float4*)(src + kg * 4);
                    float* dst = scr + buf * 4096;
                    dst[(kg * 4 + 0) * 8 + b] = v.x;
                    dst[(kg * 4 + 1) * 8 + b] = v.y;
                    dst[(kg * 4 + 2) * 8 + b] = v.z;
                    dst[(kg * 4 + 3) * 8 + b] = v.w;
                }
            }
            __syncthreads();
            const int n_loc = tid & 63;
            const int ks = tid >> 6;                   // 4 k-splits
            const int n = (n_loc >> 4) * H_ + j0A + (n_loc & 15);
            ull a0 = 0, a1 = 0, a2 = 0, a3 = 0;
            if (lay == 0) {
                const float* wp = WhL + (size_t)(ks * 128) * G_ + n;
                const float* hb = scr + ks * 128 * 8;
#pragma unroll 4
                for (int k = 0; k < 128; k++) {
                    ull w2 = pk2(wp[(size_t)k * G_]);
                    ulonglong2 hA = *(const ulonglong2*)(hb + k * 8);
                    ulonglong2 hB = *(const ulonglong2*)(hb + k * 8 + 4);
                    a0 = fma2(hA.x, w2, a0); a1 = fma2(hA.y, w2, a1);
                    a2 = fma2(hB.x, w2, a2); a3 = fma2(hB.y, w2, a3);
                }
            } else {
                const float* wp; const float* hb;
                if (ks < 2) {
                    wp = WiL + (size_t)(ks * 256) * G_ + n;
                    hb = scr + ks * 256 * 8;
                } else {
                    wp = WhL + (size_t)((ks - 2) * 256) * G_ + n;
                    hb = scr + 4096 + (ks - 2) * 256 * 8;
                }
#pragma unroll 4
                for (int k = 0; k < 256; k++) {
                    ull w2 = pk2(wp[(size_t)k * G_]);
                    ulonglong2 hA = *(const ulonglong2*)(hb + k * 8);
                    ulonglong2 hB = *(const ulonglong2*)(hb + k * 8 + 4);
                    a0 = fma2(hA.x, w2, a0); a1 = fma2(hA.y, w2, a1);
                    a2 = fma2(hB.x, w2, a2); a3 = fma2(hB.y, w2, a3);
                }
            }
            __syncthreads();                           // staging reads done
            {
                ull* rr = (ull*)scr;
                rr[(ks * 64 + n_loc) * 4 + 0] = a0;
                rr[(ks * 64 + n_loc) * 4 + 1] = a1;
                rr[(ks * 64 + n_loc) * 4 + 2] = a2;
                rr[(ks * 64 + n_loc) * 4 + 3] = a3;
            }
            __syncthreads();
            for (int slot = tid; slot < 512; slot += NT) {
                int bb = slot >> 6, nl = slot & 63;
                int g2 = nl >> 4, j2 = nl & 15;
                float v = scr[nl * 8 + bb] + scr[(64 + nl) * 8 + bb]
                        + scr[(128 + nl) * 8 + bb] + scr[(192 + nl) * 8 + bb];
                if (lay == 0)
                    v += g_XG[(size_t)(t * B_ + b0g + bb) * G_ + g2 * H_ + j0A + j2];
                else
                    v += biL[g2 * H_ + j0A + j2] + bhL[g2 * H_ + j0A + j2];
                scr[4096 + slot] = v;
            }
            __syncthreads();
            if (tid < 128) {
                int bb = tid >> 4, j2 = tid & 15;
                float gi = scr[4096 + bb * 64 + j2];
                float gf = scr[4096 + bb * 64 + 16 + j2];
                float gg = scr[4096 + bb * 64 + 32 + j2];
                float go = scr[4096 + bb * 64 + 48 + j2];
                int b = b0g + bb, j = j0A + j2;
                float cold = (t == 0) ? c0[b * H_ + j] : cL[b * H_ + j];
                float ig = 1.f / (1.f + expf(-gi));
                float fg = 1.f / (1.f + expf(-gf));
                float g2v = tanhf(gg);
                float og = 1.f / (1.f + expf(-go));
                float cy = fg * cold + ig * g2v;
                float hy = og * tanhf(cy);
                cL[b * H_ + j] = cy;
                catL[b * 2 * H_ + H_ + j] = hy;
            }
        }
        gbar(gid, t4 + 1);

        // ===== B: target = hy @ Wa_in (packed) =====
        {
            for (int i = tid; i < 1024; i += NT) {
                int b = i & 7, kg = i >> 3;
                float4 v = *(const float4*)(catL + (b0g + b) * 1024 + 512 + kg * 4);
                scr[(kg * 4 + 0) * 8 + b] = v.x;
                scr[(kg * 4 + 1) * 8 + b] = v.y;
                scr[(kg * 4 + 2) * 8 + b] = v.z;
                scr[(kg * 4 + 3) * 8 + b] = v.w;
            }
            __syncthreads();
            const int n_loc = tid & 15, ks = tid >> 4;  // 16 splits x 32 k
            ull a0 = 0, a1 = 0, a2 = 0, a3 = 0;
            const float* wp = WainL + (size_t)(ks * 32) * H_ + n0E + n_loc;
            const float* hb = scr + ks * 32 * 8;
#pragma unroll 4
            for (int k = 0; k < 32; k++) {
                ull w2 = pk2(wp[(size_t)k * H_]);
                ulonglong2 hA = *(const ulonglong2*)(hb + k * 8);
                ulonglong2 hB = *(const ulonglong2*)(hb + k * 8 + 4);
                a0 = fma2(hA.x, w2, a0); a1 = fma2(hA.y, w2, a1);
                a2 = fma2(hB.x, w2, a2); a3 = fma2(hB.y, w2, a3);
            }
            __syncthreads();                           // staging reads done
            {
                ull* rr = (ull*)scr;
                rr[(ks * 16 + n_loc) * 4 + 0] = a0;
                rr[(ks * 16 + n_loc) * 4 + 1] = a1;
                rr[(ks * 16 + n_loc) * 4 + 2] = a2;
                rr[(ks * 16 + n_loc) * 4 + 3] = a3;
            }
            __syncthreads();
            if (tid < 128) {
                int bb = tid >> 4, nn = tid & 15;
                float v = 0.f;
#pragma unroll
                for (int s2 = 0; s2 < 16; s2++) v += scr[(s2 * 16 + nn) * 8 + bb];
                tgtL[(b0g + bb) * H_ + n0E + nn] = v;
            }
        }
        gbar(gid, t4 + 2);

        // ===== C: attention — online softmax (packed), 16 s-rows per warp =====
        {
            const int b = bC, q = qC;
            const int sbase = q * 128;
            const ulonglong2* tp2 = (const ulonglong2*)(tgtL + b * H_);
            ulonglong2 tg0 = tp2[lane],      tg1 = tp2[32 + lane];
            ulonglong2 tg2 = tp2[64 + lane], tg3 = tp2[96 + lane];
            float m = -3.4e38f, z = 0.f;
            ull a0x = 0, a0y = 0, a1x = 0, a1y = 0;
            ull a2x = 0, a2y = 0, a3x = 0, a3y = 0;
#pragma unroll 4
            for (int i = 0; i < 16; i++) {
                int s = sbase + wrp * 16 + i;
                const ulonglong2* cr =
                    (const ulonglong2*)(ctx + ((size_t)s * B_ + b) * H_);
                ulonglong2 c0 = cr[lane],      c1 = cr[32 + lane];
                ulonglong2 c2 = cr[64 + lane], c3 = cr[96 + lane];
                ull pda = 0, pdb = 0;
                pda = fma2(c0.x, tg0.x, pda); pda = fma2(c0.y, tg0.y, pda);
                pda = fma2(c1.x, tg1.x, pda); pda = fma2(c1.y, tg1.y, pda);
                pdb = fma2(c2.x, tg2.x, pdb); pdb = fma2(c2.y, tg2.y, pdb);
                pdb = fma2(c3.x, tg3.x, pdb); pdb = fma2(c3.y, tg3.y, pdb);
                float p = sum2(pda) + sum2(pdb);
#pragma unroll
                for (int o = 16; o; o >>= 1) p += __shfl_xor_sync(0xffffffffu, p, o);
                if (!lane && lay == 1)
                    outa[(size_t)s * (T_ * B_) + t * B_ + b] = p;   // raw score
                float mn = fmaxf(m, p);
                float sc = expf(m - mn);
                float e  = expf(p - mn);
                z = z * sc + e;
                ull s2v = pk2(sc), e2v = pk2(e);
                a0x = fma2(a0x, s2v, mul2(c0.x, e2v));
                a0y = fma2(a0y, s2v, mul2(c0.y, e2v));
                a1x = fma2(a1x, s2v, mul2(c1.x, e2v));
                a1y = fma2(a1y, s2v, mul2(c1.y, e2v));
                a2x = fma2(a2x, s2v, mul2(c2.x, e2v));
                a2y = fma2(a2y, s2v, mul2(c2.y, e2v));
                a3x = fma2(a3x, s2v, mul2(c3.x, e2v));
                a3y = fma2(a3y, s2v, mul2(c3.y, e2v));
                m = mn;
            }
            if (!lane) { sml[wrp] = m; sml[8 + wrp] = z; }
            __syncthreads();
            if (wrp == 0) {
                float mw = (lane < 8) ? sml[lane] : -3.4e38f;
                float zw = (lane < 8) ? sml[8 + lane] : 0.f;
                float M = mw;
#pragma unroll
                for (int o = 16; o; o >>= 1)
                    M = fmaxf(M, __shfl_xor_sync(0xffffffffu, M, o));
                float cw = expf(mw - M);
                float Zb = zw * cw;
#pragma unroll
                for (int o = 16; o; o >>= 1) Zb += __shfl_xor_sync(0xffffffffu, Zb, o);
                if (lane < 8) sml[16 + lane] = cw;
                if (!lane) { pmL[b * 4 + q] = M; pzL[b * 4 + q] = Zb; }
            }
            __syncthreads();
            {
                ull cw2 = pk2(sml[16 + wrp]);
                ulonglong2* wp2 = (ulonglong2*)(scr + wrp * 512);
                ulonglong2 v;
                v.x = mul2(a0x, cw2); v.y = mul2(a0y, cw2); wp2[lane] = v;
                v.x = mul2(a1x, cw2); v.y = mul2(a1y, cw2); wp2[32 + lane] = v;
                v.x = mul2(a2x, cw2); v.y = mul2(a2y, cw2); wp2[64 + lane] = v;
                v.x = mul2(a3x, cw2); v.y = mul2(a3y, cw2); wp2[96 + lane] = v;
            }
            __syncthreads();
            for (int i = tid; i < 512; i += NT) {
                float v = 0.f;
#pragma unroll
                for (int w2 = 0; w2 < 8; w2++) v += scr[w2 * 512 + i];
                pwcL[((size_t)b * 4 + q) * H_ + i] = v;
            }
            __syncthreads();
            if (tid == 0) atom_add_acqrel(&g_bcnt[lay * B_ + b], 1u);
        }

        // ===== D: wait 4 partials of (lay,b), combine -> wc =====
        {
            const int b = bC, q = qC;
            const int k0 = q * 128;
            if (tid == 0) {
                unsigned tgt = 4u * (unsigned)(t + 1);
                while (ld_acq(&g_bcnt[lay * B_ + b]) < tgt) { }
            }
            __syncthreads();
            if (wrp == 0) {
                float M4 = (lane < 4) ? pmL[b * 4 + lane] : -3.4e38f;
                float Z4 = (lane < 4) ? pzL[b * 4 + lane] : 0.f;
                float M = M4;
#pragma unroll
                for (int o = 16; o; o >>= 1)
                    M = fmaxf(M, __shfl_xor_sync(0xffffffffu, M, o));
                float cc = expf(M4 - M);
                float Z = Z4 * cc;
#pragma unroll
                for (int o = 16; o; o >>= 1) Z += __shfl_xor_sync(0xffffffffu, Z, o);
                if (lane < 4) sml[lane] = cc;
                if (!lane) {
                    sml[4] = 1.f / Z;
                    if (lay == 1) { g_M[t * B_ + b] = M; g_iZ[t * B_ + b] = 1.f / Z; }
                }
            }
            __syncthreads();
            if (tid < 128) {
                int k = k0 + tid;
                float iZ = sml[4];
                float v = 0.f;
#pragma unroll
                for (int c2 = 0; c2 < 4; c2++)
                    v += sml[c2] * pwcL[((size_t)b * 4 + c2) * H_ + k];
                catL[b * 2 * H_ + k] = v * iZ;
            }
        }
        gbar(gid, t4 + 3);

        // ===== E: h = tanh([wc|hy] @ Wa_out) (packed, smem weights) =====
        {
            for (int i = tid; i < 2048; i += NT) {
                int b = i & 7, kg = i >> 3;   // kg 0..255
                float4 v = *(const float4*)(catL + (b0g + b) * 1024 + kg * 4);
                scr[(kg * 4 + 0) * 8 + b] = v.x;
                scr[(kg * 4 + 1) * 8 + b] = v.y;
                scr[(kg * 4 + 2) * 8 + b] = v.z;
                scr[(kg * 4 + 3) * 8 + b] = v.w;
            }
            __syncthreads();
            const int n_loc = tid & 15, ks = tid >> 4;  // 16 splits x 64 k
            ull a0 = 0, a1 = 0, a2 = 0, a3 = 0;
            const float4* w4p = (const float4*)smO + n_loc;
            const float* hb = scr + ks * 64 * 8;
#pragma unroll 4
            for (int k4 = 0; k4 < 16; k4++) {
                float4 w4 = w4p[(ks * 16 + k4) * 16];
                ull w20 = pk2(w4.x), w21 = pk2(w4.y);
                ull w22 = pk2(w4.z), w23 = pk2(w4.w);
                ulonglong2 hA, hB;
                hA = *(const ulonglong2*)(hb + (k4 * 4 + 0) * 8);
                hB = *(const ulonglong2*)(hb + (k4 * 4 + 0) * 8 + 4);
                a0 = fma2(hA.x, w20, a0); a1 = fma2(hA.y, w20, a1);
                a2 = fma2(hB.x, w20, a2); a3 = fma2(hB.y, w20, a3);
                hA = *(const ulonglong2*)(hb + (k4 * 4 + 1) * 8);
                hB = *(const ulonglong2*)(hb + (k4 * 4 + 1) * 8 + 4);
                a0 = fma2(hA.x, w21, a0); a1 = fma2(hA.y, w21, a1);
                a2 = fma2(hB.x, w21, a2); a3 = fma2(hB.y, w21, a3);
                hA = *(const ulonglong2*)(hb + (k4 * 4 + 2) * 8);
                hB = *(const ulonglong2*)(hb + (k4 * 4 + 2) * 8 + 4);
                a0 = fma2(hA.x, w22, a0); a1 = fma2(hA.y, w22, a1);
                a2 = fma2(hB.x, w22, a2); a3 = fma2(hB.y, w22, a3);
                hA = *(const ulonglong2*)(hb + (k4 * 4 + 3) * 8);
                hB = *(const ulonglong2*)(hb + (k4 * 4 + 3) * 8 + 4);
                a0 = fma2(hA.x, w23, a0); a1 = fma2(hA.y, w23, a1);
                a2 = fma2(hB.x, w23, a2); a3 = fma2(hB.y, w23, a3);
            }
            __syncthreads();                           // staging reads done
            {
                ull* rr = (ull*)scr;
                rr[(ks * 16 + n_loc) * 4 + 0] = a0;
                rr[(ks * 16 + n_loc) * 4 + 1] = a1;
                rr[(ks * 16 + n_loc) * 4 + 2] = a2;
                rr[(ks * 16 + n_loc) * 4 + 3] = a3;
            }
            __syncthreads();
            if (tid < 128) {
                int bb = tid >> 4, nn = tid & 15;
                float v = 0.f;
#pragma unroll
                for (int s2 = 0; s2 < 16; s2++) v += scr[(s2 * 16 + nn) * 8 + bb];
                v = tanhf(v);
                int b = b0g + bb, n = n0E + nn;
                hL[b * H_ + n] = v;
                if (lay == 0)
                    g_X1[((size_t)t * B_ + b) * H_ + n] = v;
                else
                    outx[(size_t)b * (T_ * H_) + (size_t)t * H_ + n] = v;
                if (t == T_ - 1) {
                    outh[lay * B_ * H_ + b * H_ + n] = v;
                    outc[lay * B_ * H_ + b * H_ + n] = cL[b * H_ + n];
                }
            }
        }
        gbar(gid, t4 + 4);

        // layer0 publishes progress for layer1's consumer gate
        if (lay == 0 && gblk == 0 && tid == 0)
            st_rel(&g_p0[oct], (unsigned)(t + 1));
    }

    // reset sync state for next launch
    if (tid == 0) {
        unsigned old = atom_add_acqrel(&g_grst[gid], 1u);
        if (old == GSZ - 1) {
            g_grst[gid] = 0;
#pragma unroll
            for (int i = 0; i < 8; i++) g_bcnt[lay * B_ + b0g + i] = 0;
            if (lay == 1) st_rel(&g_p0[oct], 0u);
            st_rel(&g_ggen[gid], 0u);
        }
    }
}

// ---------------- finalize attention output: normalize raw scores -------------
__global__ void __launch_bounds__(256) k_att(float* __restrict__ outa) {
    const int s = blockIdx.x;
    for (int i = threadIdx.x; i < T_ * B_; i += 256) {
        float v = outa[(size_t)s * (T_ * B_) + i];
        outa[(size_t)s * (T_ * B_) + i] = expf(v - g_M[i]) * g_iZ[i];
    }
}

// ---------------- host orchestration ------------------------------------------
extern "C" void kernel_launch(void* const* d_in, const int* in_sizes, int n_in,
                              void* d_out, int out_size) {
    const float* input = (const float*)d_in[0];
    const float* h0    = (const float*)d_in[1];
    const float* c0    = (const float*)d_in[2];
    const float* ctx   = (const float*)d_in[3];
    const float* Wi    = (const float*)d_in[4];
    const float* bi    = (const float*)d_in[5];
    const float* Wh    = (const float*)d_in[6];
    const float* bh    = (const float*)d_in[7];
    const float* Wain  = (const float*)d_in[8];
    const float* Waout = (const float*)d_in[9];

    float* out  = (float*)d_out;
    float* outx = out;                                   // (B,T,H)
    float* outh = out  + (size_t)B_ * T_ * H_;           // (2,B,H)
    float* outc = outh + 2 * B_ * H_;                    // (2,B,H)
    float* outa = outc + 2 * B_ * H_;                    // (S, T*B)

    const int SMEM = SMEM_FLOATS * 4;  // 98,560 B -> 2 blocks/SM
    cudaFuncSetAttribute(k_wave, cudaFuncAttributeMaxDynamicSharedMemorySize, SMEM);

    k_pre<<<dim3(G_ / 64, (T_ * B_) / 128), 256>>>(input, Wi, bi, bh);
    k_wave<<<NB, NT, SMEM>>>(ctx, Wi, bi, Wh, bh, Wain, Waout, h0, c0,
                             outx, outh, outc, outa);
    k_att<<<S_, 256>>>(outa);
}

// round 14
// speedup vs baseline: 1.3855x; 1.2749x over previous
#include <cuda_runtime.h>
#include <math.h>

#define B_ 32
#define T_ 256
#define S_ 512
#define H_ 512
#define G_ 2048   // 4*H
#define NB 256    // 8 groups x 32 blocks
#define NT 256
#define GSZ 32
#define NGRP 8

// smem floats: [0,16384) Waout slice; [16384,24576) scr; [24576,24640) sml;
//              [24640,24896) smF (lay1 local XG1 gates 2,3)
#define SCR 16384
#define SML 24576
#define SMF 24640
#define SMEM_FLOATS 24896

// ---------------- scratch: __device__ globals ---------------------------------
__device__ float g_XG[T_ * B_ * G_];       // layer0 pre-gated input (64 MB)
__device__ float g_X1[T_ * B_ * H_];       // layer0 outputs (16 MB)
__device__ float g_XG1[2 * B_ * 1024];     // lay1 gates 0,1 of XG1, dbl-buffered
__device__ float g_h[2 * B_ * H_];
__device__ float g_c[2 * B_ * H_];
__device__ float g_cat[2 * B_ * 2 * H_];   // [wc | hy]
__device__ float g_target[2 * B_ * H_];
__device__ float g_pm[2 * B_ * 4];
__device__ float g_pz[2 * B_ * 4];
__device__ float g_pwc[2 * B_ * 4 * H_];
__device__ float g_M[T_ * B_];             // layer1 softmax max
__device__ float g_iZ[T_ * B_];            // layer1 1/Z

// ---------------- sync state ---------------------------------------------------
__device__ unsigned g_gcnt[NGRP];
__device__ unsigned g_ggen[NGRP];
__device__ unsigned g_grst[NGRP];
__device__ unsigned g_bcnt[2 * B_];        // per-(layer,b) minisync (monotonic)
__device__ unsigned g_p0[4];               // layer0 progress per batch octet
__device__ unsigned g_p1[4];               // layer1 consumption progress

__device__ __forceinline__ unsigned atom_add_acqrel(unsigned* p, unsigned v) {
    unsigned old;
    asm volatile("atom.add.acq_rel.gpu.u32 %0, [%1], %2;"
                 : "=r"(old) : "l"(p), "r"(v) : "memory");
    return old;
}
__device__ __forceinline__ unsigned ld_acq(unsigned* p) {
    unsigned v;
    asm volatile("ld.acquire.gpu.u32 %0, [%1];" : "=r"(v) : "l"(p) : "memory");
    return v;
}
__device__ __forceinline__ void st_rel(unsigned* p, unsigned v) {
    asm volatile("st.release.gpu.u32 [%0], %1;" :: "l"(p), "r"(v) : "memory");
}
__device__ __forceinline__ void gbar(int gid, unsigned target) {
    __syncthreads();
    if (threadIdx.x == 0) {
        unsigned old = atom_add_acqrel(&g_gcnt[gid], 1u);
        if (old == GSZ - 1) {
            g_gcnt[gid] = 0;
            st_rel(&g_ggen[gid], target);
        } else {
            while (ld_acq(&g_ggen[gid]) != target) { }
        }
    }
    __syncthreads();
}

// ---------------- precompute XG = x @ Wi0 + (bi0 + bh0), layer 0 only ---------
__global__ void __launch_bounds__(256) k_pre(const float* __restrict__ Xin,
                                             const float* __restrict__ Wi,
                                             const float* __restrict__ bi,
                                             const float* __restrict__ bh) {
    __shared__ float As[16][128];
    __shared__ float Bs[16][64];
    const int tid = threadIdx.x;
    const int tx = tid & 15, ty = tid >> 4;
    const int n0 = blockIdx.x * 64, m0 = blockIdx.y * 128;
    const int m_l = tid & 127, kb = (tid >> 7) * 8;
    const int m = m0 + m_l;
    const int bb = m & 31, tt = m >> 5;
    const float* arow = Xin + ((size_t)bb * T_ + tt) * H_;
    const int bkk = tid >> 4, bnn = (tid & 15) * 4;

    float acc[8][4];
#pragma unroll
    for (int i = 0; i < 8; i++)
#pragma unroll
        for (int j = 0; j < 4; j++) acc[i][j] = 0.f;

    for (int k0 = 0; k0 < H_; k0 += 16) {
        float4 a0 = *(const float4*)(arow + k0 + kb);
        float4 a1 = *(const float4*)(arow + k0 + kb + 4);
        As[kb + 0][m_l] = a0.x; As[kb + 1][m_l] = a0.y;
        As[kb + 2][m_l] = a0.z; As[kb + 3][m_l] = a0.w;
        As[kb + 4][m_l] = a1.x; As[kb + 5][m_l] = a1.y;
        As[kb + 6][m_l] = a1.z; As[kb + 7][m_l] = a1.w;
        *(float4*)&Bs[bkk][bnn] =
            *(const float4*)(Wi + (size_t)(k0 + bkk) * G_ + n0 + bnn);
        __syncthreads();
#pragma unroll
        for (int kk = 0; kk < 16; kk++) {
            float4 b4  = *(const float4*)&Bs[kk][tx * 4];
            float4 alo = *(const float4*)&As[kk][ty * 8];
            float4 ahi = *(const float4*)&As[kk][ty * 8 + 4];
            float av[8] = {alo.x, alo.y, alo.z, alo.w, ahi.x, ahi.y, ahi.z, ahi.w};
#pragma unroll
            for (int i = 0; i < 8; i++) {
                acc[i][0] = fmaf(av[i], b4.x, acc[i][0]);
                acc[i][1] = fmaf(av[i], b4.y, acc[i][1]);
                acc[i][2] = fmaf(av[i], b4.z, acc[i][2]);
                acc[i][3] = fmaf(av[i], b4.w, acc[i][3]);
            }
        }
        __syncthreads();
    }
    float4 b1 = *(const float4*)(bi + n0 + tx * 4);
    float4 b2 = *(const float4*)(bh + n0 + tx * 4);
    float4 bias = {b1.x + b2.x, b1.y + b2.y, b1.z + b2.z, b1.w + b2.w};
#pragma unroll
    for (int i = 0; i < 8; i++) {
        float4 o = {acc[i][0] + bias.x, acc[i][1] + bias.y,
                    acc[i][2] + bias.z, acc[i][3] + bias.w};
        *(float4*)&g_XG[(size_t)(m0 + ty * 8 + i) * G_ + n0 + tx * 4] = o;
    }
}

// ---------------- persistent wavefront kernel: both layers concurrently -------
__global__ void __launch_bounds__(NT, 2) k_wave(
    const float* __restrict__ ctx,
    const float* __restrict__ Wi,
    const float* __restrict__ bi,
    const float* __restrict__ Wh,
    const float* __restrict__ bh,
    const float* __restrict__ Wain,
    const float* __restrict__ Waout,
    const float* __restrict__ h0,
    const float* __restrict__ c0,
    float* __restrict__ outx,
    float* __restrict__ outh,
    float* __restrict__ outc,
    float* __restrict__ outa)
{
    extern __shared__ float sm[];
    float* smO = sm;            // Waout slice, float4 index kk*16+nl
    float* scr = sm + SCR;      // 8192-float stage/reduce overlay
    float* sml = sm + SML;      // 64-float small area
    float* smF = sm + SMF;      // 256-float lay1-local XG1 gates 2,3
    const int blk = blockIdx.x, tid = threadIdx.x;
    const int lane = tid & 31, wrp = tid >> 5;
    const int gid = blk >> 5, gblk = blk & 31;
    const int lay = gid >> 2, oct = gid & 3;
    const int b0g = oct * 8;

    const int bC = b0g + (gblk >> 2), qC = gblk & 3;   // phase C/D mapping
    const int j0A = gblk * 16;                         // phase A/F j-slice
    const int n0E = gblk * 16;                         // phase B/E n-slice

    // per-layer weight pointers
    const float* WiL    = Wi    + (size_t)lay * H_ * G_;   // lay1: own Wi
    const float* Wi1    = Wi    + (size_t)H_ * G_;         // lay0-F: layer-1 Wi
    const float* biL    = bi    + lay * G_;
    const float* bhL    = bh    + lay * G_;
    const float* bi1    = bi    + G_;
    const float* bh1    = bh    + G_;
    const float* WhL    = Wh    + (size_t)lay * H_ * G_;
    const float* WainL  = Wain  + (size_t)lay * H_ * H_;
    const float* WaoutL = Waout + (size_t)lay * 2 * H_ * H_;

    float* hL   = g_h   + lay * B_ * H_;
    float* cL   = g_c   + lay * B_ * H_;
    float* catL = g_cat + lay * B_ * 2 * H_;
    float* tgtL = g_target + lay * B_ * H_;
    float* pmL  = g_pm  + lay * B_ * 4;
    float* pzL  = g_pz  + lay * B_ * 4;
    float* pwcL = g_pwc + (size_t)lay * B_ * 4 * H_;

    // ---- one-time Waout slice preload ----
    for (int idx = tid; idx < 16384; idx += NT) {
        int k = idx >> 4, nl = idx & 15;
        smO[((k >> 2) * 16 + nl) * 4 + (k & 3)] =
            WaoutL[(size_t)k * H_ + n0E + nl];
    }
    __syncthreads();

    for (int t = 0; t < T_; t++) {
        const unsigned tb = (unsigned)t * (lay == 0 ? 5 : 4);

        // ===== cross-layer gate + F' (lay1 computes gates 2,3 of XG1 locally) =
        if (lay == 1) {
            if (tid == 0) {
                unsigned tgt = (unsigned)(t + 1);
                while (ld_acq(&g_p0[oct]) < tgt) { }
            }
            __syncthreads();
            // stage x1[t] rows (8 b)
            {
                const float4* xsrc = (const float4*)(g_X1 + ((size_t)t * B_ + b0g) * H_);
                for (int i = tid; i < 1024; i += NT)
                    ((float4*)scr)[i] = xsrc[i];
            }
            __syncthreads();
            {
                const int n_loc = tid & 31;            // 2 gates x 16 j
                const int ks = tid >> 5;               // 8 splits x 64 k
                const int n = (2 + (n_loc >> 4)) * H_ + j0A + (n_loc & 15);
                float acc[8];
#pragma unroll
                for (int i = 0; i < 8; i++) acc[i] = 0.f;
                const float* wp = WiL + (size_t)(ks * 64) * G_ + n;
                const float* hb = scr;
#pragma unroll 4
                for (int k4 = 0; k4 < 16; k4++) {
                    float w0 = wp[(size_t)(k4 * 4 + 0) * G_];
                    float w1 = wp[(size_t)(k4 * 4 + 1) * G_];
                    float w2 = wp[(size_t)(k4 * 4 + 2) * G_];
                    float w3 = wp[(size_t)(k4 * 4 + 3) * G_];
#pragma unroll
                    for (int b = 0; b < 8; b++) {
                        float4 x4 = ((const float4*)(hb + b * 512))[ks * 16 + k4];
                        acc[b] = fmaf(x4.x, w0, fmaf(x4.y, w1,
                                 fmaf(x4.z, w2, fmaf(x4.w, w3, acc[b]))));
                    }
                }
                __syncthreads();                       // staging reads done
#pragma unroll
                for (int b = 0; b < 8; b++)
                    scr[((tid >> 5) * 32 + (tid & 31)) * 8 + b] = acc[b];
                __syncthreads();
                {
                    int col = tid & 31, bb = tid >> 5;
                    float v = 0.f;
#pragma unroll
                    for (int s2 = 0; s2 < 8; s2++) v += scr[(s2 * 32 + col) * 8 + bb];
                    int nn = (2 + (col >> 4)) * H_ + j0A + (col & 15);
                    v += biL[nn] + bhL[nn];
                    smF[bb * 32 + col] = v;
                }
            }
            __syncthreads();
        }

        // ===== A: gates = XG + h@Wh (K=512 both layers), fused LSTM =====
        {
            const float* hp = (t == 0) ? (h0) : hL;
            for (int i = tid; i < 1024; i += NT)
                ((float4*)scr)[i] = ((const float4*)(hp + b0g * H_))[i];
            __syncthreads();
            const int n_loc = tid & 63;
            const int ks = tid >> 6;                   // 4 k-splits x 128 k
            const int n = (n_loc >> 4) * H_ + j0A + (n_loc & 15);
            float acc[8];
#pragma unroll
            for (int i = 0; i < 8; i++) acc[i] = 0.f;
            {
                const float* wp = WhL + (size_t)(ks * 128) * G_ + n;
                const float* hb = scr + ks * 128;
#pragma unroll 4
                for (int k4 = 0; k4 < 32; k4++) {
                    float w0 = wp[(size_t)(k4 * 4 + 0) * G_];
                    float w1 = wp[(size_t)(k4 * 4 + 1) * G_];
                    float w2 = wp[(size_t)(k4 * 4 + 2) * G_];
                    float w3 = wp[(size_t)(k4 * 4 + 3) * G_];
#pragma unroll
                    for (int b = 0; b < 8; b++) {
                        float4 h4 = ((const float4*)(hb + b * 512))[k4];
                        acc[b] = fmaf(h4.x, w0, fmaf(h4.y, w1,
                                 fmaf(h4.z, w2, fmaf(h4.w, w3, acc[b]))));
                    }
                }
            }
            __syncthreads();                           // staging reads done
#pragma unroll
            for (int b = 0; b < 8; b++) scr[(ks * 64 + n_loc) * 8 + b] = acc[b];
            __syncthreads();
            for (int slot = tid; slot < 512; slot += NT) {
                int bb = slot >> 6, nl = slot & 63;
                int g2 = nl >> 4, j2 = nl & 15;
                float v = scr[nl * 8 + bb] + scr[(64 + nl) * 8 + bb]
                        + scr[(128 + nl) * 8 + bb] + scr[(192 + nl) * 8 + bb];
                if (lay == 0) {
                    v += g_XG[(size_t)(t * B_ + b0g + bb) * G_ + g2 * H_ + j0A + j2];
                } else {
                    if (g2 < 2)
                        v += g_XG1[(size_t)(t & 1) * (B_ * 1024)
                                   + (b0g + bb) * 1024 + g2 * 512 + j0A + j2];
                    else
                        v += smF[bb * 32 + (g2 - 2) * 16 + j2];
                }
                scr[4096 + slot] = v;
            }
            __syncthreads();
            if (tid < 128) {
                int bb = tid >> 4, j2 = tid & 15;
                float gi = scr[4096 + bb * 64 + j2];
                float gf = scr[4096 + bb * 64 + 16 + j2];
                float gg = scr[4096 + bb * 64 + 32 + j2];
                float go = scr[4096 + bb * 64 + 48 + j2];
                int b = b0g + bb, j = j0A + j2;
                float cold = (t == 0) ? c0[b * H_ + j] : cL[b * H_ + j];
                float ig = 1.f / (1.f + expf(-gi));
                float fg = 1.f / (1.f + expf(-gf));
                float g2v = tanhf(gg);
                float og = 1.f / (1.f + expf(-go));
                float cy = fg * cold + ig * g2v;
                float hy = og * tanhf(cy);
                cL[b * H_ + j] = cy;
                catL[b * 2 * H_ + H_ + j] = hy;
            }
        }
        gbar(gid, tb + 1);
        // lay1 publishes consumption progress (XG1[t] fully consumed)
        if (lay == 1 && gblk == 0 && tid == 0)
            st_rel(&g_p1[oct], (unsigned)(t + 1));

        // ===== B: target = hy @ Wa_in =====
        {
            for (int i = tid; i < 1024; i += NT) {
                int bb = i >> 7, f = i & 127;
                ((float4*)scr)[i] = ((const float4*)(catL + (b0g + bb) * 1024 + 512))[f];
            }
            __syncthreads();
            const int n_loc = tid & 15, ks = tid >> 4;  // 16 splits x 32 k
            float acc[8];
#pragma unroll
            for (int i = 0; i < 8; i++) acc[i] = 0.f;
            const float* wp = WainL + (size_t)(ks * 32) * H_ + n0E + n_loc;
            const float* hb = scr + ks * 32;
#pragma unroll
            for (int k4 = 0; k4 < 8; k4++) {
                float w0 = wp[(size_t)(k4 * 4 + 0) * H_];
                float w1 = wp[(size_t)(k4 * 4 + 1) * H_];
                float w2 = wp[(size_t)(k4 * 4 + 2) * H_];
                float w3 = wp[(size_t)(k4 * 4 + 3) * H_];
#pragma unroll
                for (int b = 0; b < 8; b++) {
                    float4 h4 = ((const float4*)(hb + b * 512))[k4];
                    acc[b] = fmaf(h4.x, w0, fmaf(h4.y, w1,
                             fmaf(h4.z, w2, fmaf(h4.w, w3, acc[b]))));
                }
            }
            __syncthreads();                           // staging reads done
#pragma unroll
            for (int b = 0; b < 8; b++) scr[(ks * 16 + n_loc) * 8 + b] = acc[b];
            __syncthreads();
            if (tid < 128) {
                int bb = tid >> 4, nn = tid & 15;
                float v = 0.f;
#pragma unroll
                for (int s2 = 0; s2 < 16; s2++) v += scr[(s2 * 16 + nn) * 8 + bb];
                tgtL[(b0g + bb) * H_ + n0E + nn] = v;
            }
        }
        gbar(gid, tb + 2);

        // ===== C: attention — online softmax, 16 s-rows per warp =====
        {
            const int b = bC, q = qC;
            const int sbase = q * 128;
            const float4* tp = (const float4*)(tgtL + b * H_);
            float4 tg0 = tp[lane],      tg1 = tp[32 + lane];
            float4 tg2 = tp[64 + lane], tg3 = tp[96 + lane];
            float m = -3.4e38f, z = 0.f;
            float4 a0 = {0,0,0,0}, a1 = a0, a2 = a0, a3 = a0;
#pragma unroll 4
            for (int i = 0; i < 16; i++) {
                int s = sbase + wrp * 16 + i;
                const float4* cr = (const float4*)(ctx + ((size_t)s * B_ + b) * H_);
                float4 c0v = cr[lane],      c1v = cr[32 + lane];
                float4 c2v = cr[64 + lane], c3v = cr[96 + lane];
                float p = c0v.x * tg0.x + c0v.y * tg0.y + c0v.z * tg0.z + c0v.w * tg0.w
                        + c1v.x * tg1.x + c1v.y * tg1.y + c1v.z * tg1.z + c1v.w * tg1.w
                        + c2v.x * tg2.x + c2v.y * tg2.y + c2v.z * tg2.z + c2v.w * tg2.w
                        + c3v.x * tg3.x + c3v.y * tg3.y + c3v.z * tg3.z + c3v.w * tg3.w;
#pragma unroll
                for (int o = 16; o; o >>= 1) p += __shfl_xor_sync(0xffffffffu, p, o);
                if (!lane && lay == 1)
                    outa[(size_t)s * (T_ * B_) + t * B_ + b] = p;   // raw score
                float mn = fmaxf(m, p);
                float sc = expf(m - mn);
                float e  = expf(p - mn);
                z = z * sc + e;
                a0.x = a0.x * sc + e * c0v.x; a0.y = a0.y * sc + e * c0v.y;
                a0.z = a0.z * sc + e * c0v.z; a0.w = a0.w * sc + e * c0v.w;
                a1.x = a1.x * sc + e * c1v.x; a1.y = a1.y * sc + e * c1v.y;
                a1.z = a1.z * sc + e * c1v.z; a1.w = a1.w * sc + e * c1v.w;
                a2.x = a2.x * sc + e * c2v.x; a2.y = a2.y * sc + e * c2v.y;
                a2.z = a2.z * sc + e * c2v.z; a2.w = a2.w * sc + e * c2v.w;
                a3.x = a3.x * sc + e * c3v.x; a3.y = a3.y * sc + e * c3v.y;
                a3.z = a3.z * sc + e * c3v.z; a3.w = a3.w * sc + e * c3v.w;
                m = mn;
            }
            if (!lane) { sml[wrp] = m; sml[8 + wrp] = z; }
            __syncthreads();
            if (wrp == 0) {
                float mw = (lane < 8) ? sml[lane] : -3.4e38f;
                float zw = (lane < 8) ? sml[8 + lane] : 0.f;
                float M = mw;
#pragma unroll
                for (int o = 16; o; o >>= 1)
                    M = fmaxf(M, __shfl_xor_sync(0xffffffffu, M, o));
                float cw = expf(mw - M);
                float Zb = zw * cw;
#pragma unroll
                for (int o = 16; o; o >>= 1) Zb += __shfl_xor_sync(0xffffffffu, Zb, o);
                if (lane < 8) sml[16 + lane] = cw;
                if (!lane) { pmL[b * 4 + q] = M; pzL[b * 4 + q] = Zb; }
            }
            __syncthreads();
            float cw = sml[16 + wrp];
            float4* wp4 = (float4*)(scr + wrp * 512);
            float4 s0v = {a0.x*cw, a0.y*cw, a0.z*cw, a0.w*cw};
            float4 s1v = {a1.x*cw, a1.y*cw, a1.z*cw, a1.w*cw};
            float4 s2v = {a2.x*cw, a2.y*cw, a2.z*cw, a2.w*cw};
            float4 s3v = {a3.x*cw, a3.y*cw, a3.z*cw, a3.w*cw};
            wp4[lane] = s0v; wp4[32 + lane] = s1v;
            wp4[64 + lane] = s2v; wp4[96 + lane] = s3v;
            __syncthreads();
            for (int i = tid; i < 512; i += NT) {
                float v = 0.f;
#pragma unroll
                for (int w2 = 0; w2 < 8; w2++) v += scr[w2 * 512 + i];
                pwcL[((size_t)b * 4 + q) * H_ + i] = v;
            }
            __syncthreads();
            if (tid == 0) atom_add_acqrel(&g_bcnt[lay * B_ + b], 1u);
        }

        // ===== D: wait 4 partials of (lay,b), combine -> wc =====
        {
            const int b = bC, q = qC;
            const int k0 = q * 128;
            if (tid == 0) {
                unsigned tgt = 4u * (unsigned)(t + 1);
                while (ld_acq(&g_bcnt[lay * B_ + b]) < tgt) { }
            }
            __syncthreads();
            if (wrp == 0) {
                float M4 = (lane < 4) ? pmL[b * 4 + lane] : -3.4e38f;
                float Z4 = (lane < 4) ? pzL[b * 4 + lane] : 0.f;
                float M = M4;
#pragma unroll
                for (int o = 16; o; o >>= 1)
                    M = fmaxf(M, __shfl_xor_sync(0xffffffffu, M, o));
                float cc = expf(M4 - M);
                float Z = Z4 * cc;
#pragma unroll
                for (int o = 16; o; o >>= 1) Z += __shfl_xor_sync(0xffffffffu, Z, o);
                if (lane < 4) sml[lane] = cc;
                if (!lane) {
                    sml[4] = 1.f / Z;
                    if (lay == 1) { g_M[t * B_ + b] = M; g_iZ[t * B_ + b] = 1.f / Z; }
                }
            }
            __syncthreads();
            if (tid < 128) {
                int k = k0 + tid;
                float iZ = sml[4];
                float v = 0.f;
#pragma unroll
                for (int c2 = 0; c2 < 4; c2++)
                    v += sml[c2] * pwcL[((size_t)b * 4 + c2) * H_ + k];
                catL[b * 2 * H_ + k] = v * iZ;
            }
        }
        gbar(gid, tb + 3);

        // ===== E: h = tanh([wc|hy] @ Wa_out) (smem weights), outputs =====
        {
            for (int i = tid; i < 2048; i += NT)
                ((float4*)scr)[i] = ((const float4*)(catL + b0g * 1024))[i];
            __syncthreads();
            const int n_loc = tid & 15, ks = tid >> 4;  // 16 splits x 64 k
            float acc[8];
#pragma unroll
            for (int i = 0; i < 8; i++) acc[i] = 0.f;
            const float4* w4p = (const float4*)smO + n_loc;
#pragma unroll 4
            for (int k4 = 0; k4 < 16; k4++) {
                float4 w4 = w4p[(ks * 16 + k4) * 16];
#pragma unroll
                for (int b = 0; b < 8; b++) {
                    float4 h4 = ((const float4*)(scr + b * 1024))[ks * 16 + k4];
                    acc[b] = fmaf(h4.x, w4.x, fmaf(h4.y, w4.y,
                             fmaf(h4.z, w4.z, fmaf(h4.w, w4.w, acc[b]))));
                }
            }
            __syncthreads();                           // staging reads done
#pragma unroll
            for (int b = 0; b < 8; b++) scr[(ks * 16 + n_loc) * 8 + b] = acc[b];
            __syncthreads();
            if (tid < 128) {
                int bb = tid >> 4, nn = tid & 15;
                float v = 0.f;
#pragma unroll
                for (int s2 = 0; s2 < 16; s2++) v += scr[(s2 * 16 + nn) * 8 + bb];
                v = tanhf(v);
                int b = b0g + bb, n = n0E + nn;
                hL[b * H_ + n] = v;
                if (lay == 0)
                    g_X1[((size_t)t * B_ + b) * H_ + n] = v;
                else
                    outx[(size_t)b * (T_ * H_) + (size_t)t * H_ + n] = v;
                if (t == T_ - 1) {
                    outh[lay * B_ * H_ + b * H_ + n] = v;
                    outc[lay * B_ * H_ + b * H_ + n] = cL[b * H_ + n];
                }
            }
        }
        gbar(gid, tb + 4);

        // ===== F (lay0 only): XG1[t] gates 0,1 = x1[t] @ Wi1 + biases =====
        if (lay == 0) {
            // back-throttle: don't overwrite buffer (t&1) until lay1 consumed t-2
            if (tid == 0 && t >= 2) {
                unsigned tgt = (unsigned)(t - 1);
                while (ld_acq(&g_p1[oct]) < tgt) { }
            }
            __syncthreads();
            {
                const float4* xsrc = (const float4*)(g_X1 + ((size_t)t * B_ + b0g) * H_);
                for (int i = tid; i < 1024; i += NT)
                    ((float4*)scr)[i] = xsrc[i];
            }
            __syncthreads();
            {
                const int n_loc = tid & 31;            // 2 gates x 16 j
                const int ks = tid >> 5;               // 8 splits x 64 k
                const int n = (n_loc >> 4) * H_ + j0A + (n_loc & 15);
                float acc[8];
#pragma unroll
                for (int i = 0; i < 8; i++) acc[i] = 0.f;
                const float* wp = Wi1 + (size_t)(ks * 64) * G_ + n;
#pragma unroll 4
                for (int k4 = 0; k4 < 16; k4++) {
                    float w0 = wp[(size_t)(k4 * 4 + 0) * G_];
                    float w1 = wp[(size_t)(k4 * 4 + 1) * G_];
                    float w2 = wp[(size_t)(k4 * 4 + 2) * G_];
                    float w3 = wp[(size_t)(k4 * 4 + 3) * G_];
#pragma unroll
                    for (int b = 0; b < 8; b++) {
                        float4 x4 = ((const float4*)(scr + b * 512))[ks * 16 + k4];
                        acc[b] = fmaf(x4.x, w0, fmaf(x4.y, w1,
                                 fmaf(x4.z, w2, fmaf(x4.w, w3, acc[b]))));
                    }
                }
                __syncthreads();                       // staging reads done
#pragma unroll
                for (int b = 0; b < 8; b++)
                    scr[((tid >> 5) * 32 + (tid & 31)) * 8 + b] = acc[b];
                __syncthreads();
                {
                    int col = tid & 31, bb = tid >> 5;
                    float v = 0.f;
#pragma unroll
                    for (int s2 = 0; s2 < 8; s2++) v += scr[(s2 * 32 + col) * 8 + bb];
                    int g01 = col >> 4, jj = col & 15;
                    int nn = g01 * H_ + j0A + jj;
                    v += bi1[nn] + bh1[nn];
                    g_XG1[(size_t)(t & 1) * (B_ * 1024)
                          + (b0g + bb) * 1024 + g01 * 512 + j0A + jj] = v;
                }
            }
            gbar(gid, tb + 5);
            if (gblk == 0 && tid == 0)
                st_rel(&g_p0[oct], (unsigned)(t + 1));
        }
    }

    // reset sync state for next launch
    if (tid == 0) {
        unsigned old = atom_add_acqrel(&g_grst[gid], 1u);
        if (old == GSZ - 1) {
            g_grst[gid] = 0;
#pragma unroll
            for (int i = 0; i < 8; i++) g_bcnt[lay * B_ + b0g + i] = 0;
            if (lay == 1) { st_rel(&g_p0[oct], 0u); st_rel(&g_p1[oct], 0u); }
            st_rel(&g_ggen[gid], 0u);
        }
    }
}

// ---------------- finalize attention output: normalize raw scores -------------
__global__ void __launch_bounds__(256) k_att(float* __restrict__ outa) {
    const int s = blockIdx.x;
    for (int i = threadIdx.x; i < T_ * B_; i += 256) {
        float v = outa[(size_t)s * (T_ * B_) + i];
        outa[(size_t)s * (T_ * B_) + i] = expf(v - g_M[i]) * g_iZ[i];
    }
}

// ---------------- host orchestration ------------------------------------------
extern "C" void kernel_launch(void* const* d_in, const int* in_sizes, int n_in,
                              void* d_out, int out_size) {
    const float* input = (const float*)d_in[0];
    const float* h0    = (const float*)d_in[1];
    const float* c0    = (const float*)d_in[2];
    const float* ctx   = (const float*)d_in[3];
    const float* Wi    = (const float*)d_in[4];
    const float* bi    = (const float*)d_in[5];
    const float* Wh    = (const float*)d_in[6];
    const float* bh    = (const float*)d_in[7];
    const float* Wain  = (const float*)d_in[8];
    const float* Waout = (const float*)d_in[9];

    float* out  = (float*)d_out;
    float* outx = out;                                   // (B,T,H)
    float* outh = out  + (size_t)B_ * T_ * H_;           // (2,B,H)
    float* outc = outh + 2 * B_ * H_;                    // (2,B,H)
    float* outa = outc + 2 * B_ * H_;                    // (S, T*B)

    const int SMEM = SMEM_FLOATS * 4;  // 99,584 B -> 2 blocks/SM
    cudaFuncSetAttribute(k_wave, cudaFuncAttributeMaxDynamicSharedMemorySize, SMEM);

    k_pre<<<dim3(G_ / 64, (T_ * B_) / 128), 256>>>(input, Wi, bi, bh);
    k_wave<<<NB, NT, SMEM>>>(ctx, Wi, bi, Wh, bh, Wain, Waout, h0, c0,
                             outx, outh, outc, outa);
    k_att<<<S_, 256>>>(outa);
}

// round 15
// speedup vs baseline: 1.3873x; 1.0013x over previous
#include <cuda_runtime.h>
#include <math.h>

#define B_ 32
#define T_ 256
#define S_ 512
#define H_ 512
#define G_ 2048   // 4*H
#define NB 256    // 8 groups x 32 blocks
#define NT 256
#define GSZ 32
#define NGRP 8

// smem floats: [0,16384) Waout slice; [16384,24576) scr; [24576,24640) sml;
//              [24640,24896) smF (lay1 local XG1 gates 2,3)
#define SCR 16384
#define SML 24576
#define SMF 24640
#define SMEM_FLOATS 24896

// ---------------- scratch: __device__ globals ---------------------------------
__device__ float g_XG[T_ * B_ * G_];       // layer0 pre-gated input (64 MB)
__device__ float g_X1[T_ * B_ * H_];       // layer0 outputs (16 MB)
__device__ float g_XG1[8 * B_ * 1024];     // lay1 gates 0,1 of XG1, 8-deep ring
__device__ float g_h[2 * B_ * H_];
__device__ float g_c[2 * B_ * H_];
__device__ float g_cat[2 * B_ * 2 * H_];   // [wc | hy]
__device__ float g_target[2 * B_ * H_];
__device__ float g_pm[2 * B_ * 4];
__device__ float g_pz[2 * B_ * 4];
__device__ float g_pwc[2 * B_ * 4 * H_];
__device__ float g_M[T_ * B_];             // layer1 softmax max
__device__ float g_iZ[T_ * B_];            // layer1 1/Z

// ---------------- sync state ---------------------------------------------------
__device__ unsigned g_gcnt[NGRP];
__device__ unsigned g_ggen[NGRP];
__device__ unsigned g_grst[NGRP];
__device__ unsigned g_bcnt[2 * B_];        // per-(layer,b) minisync (monotonic)
__device__ unsigned g_p0c[4];              // lay0 F arrivals: 32 per step
__device__ unsigned g_p1[4];               // layer1 consumption progress

__device__ __forceinline__ unsigned atom_add_acqrel(unsigned* p, unsigned v) {
    unsigned old;
    asm volatile("atom.add.acq_rel.gpu.u32 %0, [%1], %2;"
                 : "=r"(old) : "l"(p), "r"(v) : "memory");
    return old;
}
__device__ __forceinline__ unsigned ld_acq(unsigned* p) {
    unsigned v;
    asm volatile("ld.acquire.gpu.u32 %0, [%1];" : "=r"(v) : "l"(p) : "memory");
    return v;
}
__device__ __forceinline__ void st_rel(unsigned* p, unsigned v) {
    asm volatile("st.release.gpu.u32 [%0], %1;" :: "l"(p), "r"(v) : "memory");
}
__device__ __forceinline__ void gbar(int gid, unsigned target) {
    __syncthreads();
    if (threadIdx.x == 0) {
        unsigned old = atom_add_acqrel(&g_gcnt[gid], 1u);
        if (old == GSZ - 1) {
            g_gcnt[gid] = 0;
            st_rel(&g_ggen[gid], target);
        } else {
            while (ld_acq(&g_ggen[gid]) != target) { }
        }
    }
    __syncthreads();
}

// ---------------- precompute XG = x @ Wi0 + (bi0 + bh0), layer 0 only ---------
__global__ void __launch_bounds__(256) k_pre(const float* __restrict__ Xin,
                                             const float* __restrict__ Wi,
                                             const float* __restrict__ bi,
                                             const float* __restrict__ bh) {
    __shared__ float As[16][128];
    __shared__ float Bs[16][64];
    const int tid = threadIdx.x;
    const int tx = tid & 15, ty = tid >> 4;
    const int n0 = blockIdx.x * 64, m0 = blockIdx.y * 128;
    const int m_l = tid & 127, kb = (tid >> 7) * 8;
    const int m = m0 + m_l;
    const int bb = m & 31, tt = m >> 5;
    const float* arow = Xin + ((size_t)bb * T_ + tt) * H_;
    const int bkk = tid >> 4, bnn = (tid & 15) * 4;

    float acc[8][4];
#pragma unroll
    for (int i = 0; i < 8; i++)
#pragma unroll
        for (int j = 0; j < 4; j++) acc[i][j] = 0.f;

    for (int k0 = 0; k0 < H_; k0 += 16) {
        float4 a0 = *(const float4*)(arow + k0 + kb);
        float4 a1 = *(const float4*)(arow + k0 + kb + 4);
        As[kb + 0][m_l] = a0.x; As[kb + 1][m_l] = a0.y;
        As[kb + 2][m_l] = a0.z; As[kb + 3][m_l] = a0.w;
        As[kb + 4][m_l] = a1.x; As[kb + 5][m_l] = a1.y;
        As[kb + 6][m_l] = a1.z; As[kb + 7][m_l] = a1.w;
        *(float4*)&Bs[bkk][bnn] =
            *(const float4*)(Wi + (size_t)(k0 + bkk) * G_ + n0 + bnn);
        __syncthreads();
#pragma unroll
        for (int kk = 0; kk < 16; kk++) {
            float4 b4  = *(const float4*)&Bs[kk][tx * 4];
            float4 alo = *(const float4*)&As[kk][ty * 8];
            float4 ahi = *(const float4*)&As[kk][ty * 8 + 4];
            float av[8] = {alo.x, alo.y, alo.z, alo.w, ahi.x, ahi.y, ahi.z, ahi.w};
#pragma unroll
            for (int i = 0; i < 8; i++) {
                acc[i][0] = fmaf(av[i], b4.x, acc[i][0]);
                acc[i][1] = fmaf(av[i], b4.y, acc[i][1]);
                acc[i][2] = fmaf(av[i], b4.z, acc[i][2]);
                acc[i][3] = fmaf(av[i], b4.w, acc[i][3]);
            }
        }
        __syncthreads();
    }
    float4 b1 = *(const float4*)(bi + n0 + tx * 4);
    float4 b2 = *(const float4*)(bh + n0 + tx * 4);
    float4 bias = {b1.x + b2.x, b1.y + b2.y, b1.z + b2.z, b1.w + b2.w};
#pragma unroll
    for (int i = 0; i < 8; i++) {
        float4 o = {acc[i][0] + bias.x, acc[i][1] + bias.y,
                    acc[i][2] + bias.z, acc[i][3] + bias.w};
        *(float4*)&g_XG[(size_t)(m0 + ty * 8 + i) * G_ + n0 + tx * 4] = o;
    }
}

// ---------------- persistent wavefront kernel: both layers concurrently -------
__global__ void __launch_bounds__(NT, 2) k_wave(
    const float* __restrict__ ctx,
    const float* __restrict__ Wi,
    const float* __restrict__ bi,
    const float* __restrict__ Wh,
    const float* __restrict__ bh,
    const float* __restrict__ Wain,
    const float* __restrict__ Waout,
    const float* __restrict__ h0,
    const float* __restrict__ c0,
    float* __restrict__ outx,
    float* __restrict__ outh,
    float* __restrict__ outc,
    float* __restrict__ outa)
{
    extern __shared__ float sm[];
    float* smO = sm;            // Waout slice, float4 index kk*16+nl
    float* scr = sm + SCR;      // 8192-float stage/reduce overlay
    float* sml = sm + SML;      // 64-float small area
    float* smF = sm + SMF;      // 256-float lay1-local XG1 gates 2,3
    const int blk = blockIdx.x, tid = threadIdx.x;
    const int lane = tid & 31, wrp = tid >> 5;
    const int gid = blk >> 5, gblk = blk & 31;
    const int lay = gid >> 2, oct = gid & 3;
    const int b0g = oct * 8;

    const int bC = b0g + (gblk >> 2), qC = gblk & 3;   // phase C/D mapping
    const int j0A = gblk * 16;                         // phase A/F j-slice
    const int n0E = gblk * 16;                         // phase B/E n-slice

    // per-layer weight pointers
    const float* WiL    = Wi    + (size_t)lay * H_ * G_;   // lay1: own Wi
    const float* Wi1    = Wi    + (size_t)H_ * G_;         // lay0-F: layer-1 Wi
    const float* biL    = bi    + lay * G_;
    const float* bhL    = bh    + lay * G_;
    const float* bi1    = bi    + G_;
    const float* bh1    = bh    + G_;
    const float* WhL    = Wh    + (size_t)lay * H_ * G_;
    const float* WainL  = Wain  + (size_t)lay * H_ * H_;
    const float* WaoutL = Waout + (size_t)lay * 2 * H_ * H_;

    float* hL   = g_h   + lay * B_ * H_;
    float* cL   = g_c   + lay * B_ * H_;
    float* catL = g_cat + lay * B_ * 2 * H_;
    float* tgtL = g_target + lay * B_ * H_;
    float* pmL  = g_pm  + lay * B_ * 4;
    float* pzL  = g_pz  + lay * B_ * 4;
    float* pwcL = g_pwc + (size_t)lay * B_ * 4 * H_;

    // ---- one-time Waout slice preload ----
    for (int idx = tid; idx < 16384; idx += NT) {
        int k = idx >> 4, nl = idx & 15;
        smO[((k >> 2) * 16 + nl) * 4 + (k & 3)] =
            WaoutL[(size_t)k * H_ + n0E + nl];
    }
    __syncthreads();

    for (int t = 0; t < T_; t++) {
        const unsigned tb = (unsigned)t * 4;

        // ===== cross-layer gate + F' (lay1 computes gates 2,3 of XG1 locally) =
        if (lay == 1) {
            if (tid == 0) {
                unsigned tgt = 32u * (unsigned)(t + 1);
                while (ld_acq(&g_p0c[oct]) < tgt) { }
            }
            __syncthreads();
            // stage x1[t] rows (8 b)
            {
                const float4* xsrc = (const float4*)(g_X1 + ((size_t)t * B_ + b0g) * H_);
                for (int i = tid; i < 1024; i += NT)
                    ((float4*)scr)[i] = xsrc[i];
            }
            __syncthreads();
            {
                const int n_loc = tid & 31;            // 2 gates x 16 j
                const int ks = tid >> 5;               // 8 splits x 64 k
                const int n = (2 + (n_loc >> 4)) * H_ + j0A + (n_loc & 15);
                float acc[8];
#pragma unroll
                for (int i = 0; i < 8; i++) acc[i] = 0.f;
                const float* wp = WiL + (size_t)(ks * 64) * G_ + n;
                const float* hb = scr;
#pragma unroll 4
                for (int k4 = 0; k4 < 16; k4++) {
                    float w0 = wp[(size_t)(k4 * 4 + 0) * G_];
                    float w1 = wp[(size_t)(k4 * 4 + 1) * G_];
                    float w2 = wp[(size_t)(k4 * 4 + 2) * G_];
                    float w3 = wp[(size_t)(k4 * 4 + 3) * G_];
#pragma unroll
                    for (int b = 0; b < 8; b++) {
                        float4 x4 = ((const float4*)(hb + b * 512))[ks * 16 + k4];
                        acc[b] = fmaf(x4.x, w0, fmaf(x4.y, w1,
                                 fmaf(x4.z, w2, fmaf(x4.w, w3, acc[b]))));
                    }
                }
                __syncthreads();                       // staging reads done
#pragma unroll
                for (int b = 0; b < 8; b++)
                    scr[((tid >> 5) * 32 + (tid & 31)) * 8 + b] = acc[b];
                __syncthreads();
                {
                    int col = tid & 31, bb = tid >> 5;
                    float v = 0.f;
#pragma unroll
                    for (int s2 = 0; s2 < 8; s2++) v += scr[(s2 * 32 + col) * 8 + bb];
                    int nn = (2 + (col >> 4)) * H_ + j0A + (col & 15);
                    v += biL[nn] + bhL[nn];
                    smF[bb * 32 + col] = v;
                }
            }
            __syncthreads();
        }

        // ===== A: gates = XG + h@Wh (K=512 both layers), fused LSTM =====
        {
            const float* hp = (t == 0) ? (h0) : hL;
            for (int i = tid; i < 1024; i += NT)
                ((float4*)scr)[i] = ((const float4*)(hp + b0g * H_))[i];
            __syncthreads();
            const int n_loc = tid & 63;
            const int ks = tid >> 6;                   // 4 k-splits x 128 k
            const int n = (n_loc >> 4) * H_ + j0A + (n_loc & 15);
            float acc[8];
#pragma unroll
            for (int i = 0; i < 8; i++) acc[i] = 0.f;
            {
                const float* wp = WhL + (size_t)(ks * 128) * G_ + n;
                const float* hb = scr + ks * 128;
#pragma unroll 4
                for (int k4 = 0; k4 < 32; k4++) {
                    float w0 = wp[(size_t)(k4 * 4 + 0) * G_];
                    float w1 = wp[(size_t)(k4 * 4 + 1) * G_];
                    float w2 = wp[(size_t)(k4 * 4 + 2) * G_];
                    float w3 = wp[(size_t)(k4 * 4 + 3) * G_];
#pragma unroll
                    for (int b = 0; b < 8; b++) {
                        float4 h4 = ((const float4*)(hb + b * 512))[k4];
                        acc[b] = fmaf(h4.x, w0, fmaf(h4.y, w1,
                                 fmaf(h4.z, w2, fmaf(h4.w, w3, acc[b]))));
                    }
                }
            }
            __syncthreads();                           // staging reads done
#pragma unroll
            for (int b = 0; b < 8; b++) scr[(ks * 64 + n_loc) * 8 + b] = acc[b];
            __syncthreads();
            for (int slot = tid; slot < 512; slot += NT) {
                int bb = slot >> 6, nl = slot & 63;
                int g2 = nl >> 4, j2 = nl & 15;
                float v = scr[nl * 8 + bb] + scr[(64 + nl) * 8 + bb]
                        + scr[(128 + nl) * 8 + bb] + scr[(192 + nl) * 8 + bb];
                if (lay == 0) {
                    v += g_XG[(size_t)(t * B_ + b0g + bb) * G_ + g2 * H_ + j0A + j2];
                } else {
                    if (g2 < 2)
                        v += g_XG1[(size_t)(t & 7) * (B_ * 1024)
                                   + (b0g + bb) * 1024 + g2 * 512 + j0A + j2];
                    else
                        v += smF[bb * 32 + (g2 - 2) * 16 + j2];
                }
                scr[4096 + slot] = v;
            }
            __syncthreads();
            if (tid < 128) {
                int bb = tid >> 4, j2 = tid & 15;
                float gi = scr[4096 + bb * 64 + j2];
                float gf = scr[4096 + bb * 64 + 16 + j2];
                float gg = scr[4096 + bb * 64 + 32 + j2];
                float go = scr[4096 + bb * 64 + 48 + j2];
                int b = b0g + bb, j = j0A + j2;
                float cold = (t == 0) ? c0[b * H_ + j] : cL[b * H_ + j];
                float ig = 1.f / (1.f + expf(-gi));
                float fg = 1.f / (1.f + expf(-gf));
                float g2v = tanhf(gg);
                float og = 1.f / (1.f + expf(-go));
                float cy = fg * cold + ig * g2v;
                float hy = og * tanhf(cy);
                cL[b * H_ + j] = cy;
                catL[b * 2 * H_ + H_ + j] = hy;
            }
        }
        gbar(gid, tb + 1);
        // lay1 publishes consumption progress (XG1[t] fully consumed)
        if (lay == 1 && gblk == 0 && tid == 0)
            st_rel(&g_p1[oct], (unsigned)(t + 1));

        // ===== B: target = hy @ Wa_in =====
        {
            for (int i = tid; i < 1024; i += NT) {
                int bb = i >> 7, f = i & 127;
                ((float4*)scr)[i] = ((const float4*)(catL + (b0g + bb) * 1024 + 512))[f];
            }
            __syncthreads();
            const int n_loc = tid & 15, ks = tid >> 4;  // 16 splits x 32 k
            float acc[8];
#pragma unroll
            for (int i = 0; i < 8; i++) acc[i] = 0.f;
            const float* wp = WainL + (size_t)(ks * 32) * H_ + n0E + n_loc;
            const float* hb = scr + ks * 32;
#pragma unroll
            for (int k4 = 0; k4 < 8; k4++) {
                float w0 = wp[(size_t)(k4 * 4 + 0) * H_];
                float w1 = wp[(size_t)(k4 * 4 + 1) * H_];
                float w2 = wp[(size_t)(k4 * 4 + 2) * H_];
                float w3 = wp[(size_t)(k4 * 4 + 3) * H_];
#pragma unroll
                for (int b = 0; b < 8; b++) {
                    float4 h4 = ((const float4*)(hb + b * 512))[k4];
                    acc[b] = fmaf(h4.x, w0, fmaf(h4.y, w1,
                             fmaf(h4.z, w2, fmaf(h4.w, w3, acc[b]))));
                }
            }
            __syncthreads();                           // staging reads done
#pragma unroll
            for (int b = 0; b < 8; b++) scr[(ks * 16 + n_loc) * 8 + b] = acc[b];
            __syncthreads();
            if (tid < 128) {
                int bb = tid >> 4, nn = tid & 15;
                float v = 0.f;
#pragma unroll
                for (int s2 = 0; s2 < 16; s2++) v += scr[(s2 * 16 + nn) * 8 + bb];
                tgtL[(b0g + bb) * H_ + n0E + nn] = v;
            }
        }
        gbar(gid, tb + 2);

        // ===== C: attention — online softmax, 16 s-rows per warp =====
        {
            const int b = bC, q = qC;
            const int sbase = q * 128;
            const float4* tp = (const float4*)(tgtL + b * H_);
            float4 tg0 = tp[lane],      tg1 = tp[32 + lane];
            float4 tg2 = tp[64 + lane], tg3 = tp[96 + lane];
            float m = -3.4e38f, z = 0.f;
            float4 a0 = {0,0,0,0}, a1 = a0, a2 = a0, a3 = a0;
#pragma unroll 4
            for (int i = 0; i < 16; i++) {
                int s = sbase + wrp * 16 + i;
                const float4* cr = (const float4*)(ctx + ((size_t)s * B_ + b) * H_);
                float4 c0v = cr[lane],      c1v = cr[32 + lane];
                float4 c2v = cr[64 + lane], c3v = cr[96 + lane];
                float p = c0v.x * tg0.x + c0v.y * tg0.y + c0v.z * tg0.z + c0v.w * tg0.w
                        + c1v.x * tg1.x + c1v.y * tg1.y + c1v.z * tg1.z + c1v.w * tg1.w
                        + c2v.x * tg2.x + c2v.y * tg2.y + c2v.z * tg2.z + c2v.w * tg2.w
                        + c3v.x * tg3.x + c3v.y * tg3.y + c3v.z * tg3.z + c3v.w * tg3.w;
#pragma unroll
                for (int o = 16; o; o >>= 1) p += __shfl_xor_sync(0xffffffffu, p, o);
                if (!lane && lay == 1)
                    outa[(size_t)s * (T_ * B_) + t * B_ + b] = p;   // raw score
                float mn = fmaxf(m, p);
                float sc = expf(m - mn);
                float e  = expf(p - mn);
                z = z * sc + e;
                a0.x = a0.x * sc + e * c0v.x; a0.y = a0.y * sc + e * c0v.y;
                a0.z = a0.z * sc + e * c0v.z; a0.w = a0.w * sc + e * c0v.w;
                a1.x = a1.x * sc + e * c1v.x; a1.y = a1.y * sc + e * c1v.y;
                a1.z = a1.z * sc + e * c1v.z; a1.w = a1.w * sc + e * c1v.w;
                a2.x = a2.x * sc + e * c2v.x; a2.y = a2.y * sc + e * c2v.y;
                a2.z = a2.z * sc + e * c2v.z; a2.w = a2.w * sc + e * c2v.w;
                a3.x = a3.x * sc + e * c3v.x; a3.y = a3.y * sc + e * c3v.y;
                a3.z = a3.z * sc + e * c3v.z; a3.w = a3.w * sc + e * c3v.w;
                m = mn;
            }
            if (!lane) { sml[wrp] = m; sml[8 + wrp] = z; }
            __syncthreads();
            if (wrp == 0) {
                float mw = (lane < 8) ? sml[lane] : -3.4e38f;
                float zw = (lane < 8) ? sml[8 + lane] : 0.f;
                float M = mw;
#pragma unroll
                for (int o = 16; o; o >>= 1)
                    M = fmaxf(M, __shfl_xor_sync(0xffffffffu, M, o));
                float cw = expf(mw - M);
                float Zb = zw * cw;
#pragma unroll
                for (int o = 16; o; o >>= 1) Zb += __shfl_xor_sync(0xffffffffu, Zb, o);
                if (lane < 8) sml[16 + lane] = cw;
                if (!lane) { pmL[b * 4 + q] = M; pzL[b * 4 + q] = Zb; }
            }
            __syncthreads();
            float cw = sml[16 + wrp];
            float4* wp4 = (float4*)(scr + wrp * 512);
            float4 s0v = {a0.x*cw, a0.y*cw, a0.z*cw, a0.w*cw};
            float4 s1v = {a1.x*cw, a1.y*cw, a1.z*cw, a1.w*cw};
            float4 s2v = {a2.x*cw, a2.y*cw, a2.z*cw, a2.w*cw};
            float4 s3v = {a3.x*cw, a3.y*cw, a3.z*cw, a3.w*cw};
            wp4[lane] = s0v; wp4[32 + lane] = s1v;
            wp4[64 + lane] = s2v; wp4[96 + lane] = s3v;
            __syncthreads();
            for (int i = tid; i < 512; i += NT) {
                float v = 0.f;
#pragma unroll
                for (int w2 = 0; w2 < 8; w2++) v += scr[w2 * 512 + i];
                pwcL[((size_t)b * 4 + q) * H_ + i] = v;
            }
            __syncthreads();
            if (tid == 0) atom_add_acqrel(&g_bcnt[lay * B_ + b], 1u);
        }

        // ===== D: wait 4 partials of (lay,b), combine -> wc =====
        {
            const int b = bC, q = qC;
            const int k0 = q * 128;
            if (tid == 0) {
                unsigned tgt = 4u * (unsigned)(t + 1);
                while (ld_acq(&g_bcnt[lay * B_ + b]) < tgt) { }
            }
            __syncthreads();
            if (wrp == 0) {
                float M4 = (lane < 4) ? pmL[b * 4 + lane] : -3.4e38f;
                float Z4 = (lane < 4) ? pzL[b * 4 + lane] : 0.f;
                float M = M4;
#pragma unroll
                for (int o = 16; o; o >>= 1)
                    M = fmaxf(M, __shfl_xor_sync(0xffffffffu, M, o));
                float cc = expf(M4 - M);
                float Z = Z4 * cc;
#pragma unroll
                for (int o = 16; o; o >>= 1) Z += __shfl_xor_sync(0xffffffffu, Z, o);
                if (lane < 4) sml[lane] = cc;
                if (!lane) {
                    sml[4] = 1.f / Z;
                    if (lay == 1) { g_M[t * B_ + b] = M; g_iZ[t * B_ + b] = 1.f / Z; }
                }
            }
            __syncthreads();
            if (tid < 128) {
                int k = k0 + tid;
                float iZ = sml[4];
                float v = 0.f;
#pragma unroll
                for (int c2 = 0; c2 < 4; c2++)
                    v += sml[c2] * pwcL[((size_t)b * 4 + c2) * H_ + k];
                catL[b * 2 * H_ + k] = v * iZ;
            }
        }
        gbar(gid, tb + 3);

        // ===== E: h = tanh([wc|hy] @ Wa_out) (smem weights), outputs =====
        {
            for (int i = tid; i < 2048; i += NT)
                ((float4*)scr)[i] = ((const float4*)(catL + b0g * 1024))[i];
            __syncthreads();
            const int n_loc = tid & 15, ks = tid >> 4;  // 16 splits x 64 k
            float acc[8];
#pragma unroll
            for (int i = 0; i < 8; i++) acc[i] = 0.f;
            const float4* w4p = (const float4*)smO + n_loc;
#pragma unroll 4
            for (int k4 = 0; k4 < 16; k4++) {
                float4 w4 = w4p[(ks * 16 + k4) * 16];
#pragma unroll
                for (int b = 0; b < 8; b++) {
                    float4 h4 = ((const float4*)(scr + b * 1024))[ks * 16 + k4];
                    acc[b] = fmaf(h4.x, w4.x, fmaf(h4.y, w4.y,
                             fmaf(h4.z, w4.z, fmaf(h4.w, w4.w, acc[b]))));
                }
            }
            __syncthreads();                           // staging reads done
#pragma unroll
            for (int b = 0; b < 8; b++) scr[(ks * 16 + n_loc) * 8 + b] = acc[b];
            __syncthreads();
            if (tid < 128) {
                int bb = tid >> 4, nn = tid & 15;
                float v = 0.f;
#pragma unroll
                for (int s2 = 0; s2 < 16; s2++) v += scr[(s2 * 16 + nn) * 8 + bb];
                v = tanhf(v);
                int b = b0g + bb, n = n0E + nn;
                hL[b * H_ + n] = v;
                if (lay == 0)
                    g_X1[((size_t)t * B_ + b) * H_ + n] = v;
                else
                    outx[(size_t)b * (T_ * H_) + (size_t)t * H_ + n] = v;
                if (t == T_ - 1) {
                    outh[lay * B_ * H_ + b * H_ + n] = v;
                    outc[lay * B_ * H_ + b * H_ + n] = cL[b * H_ + n];
                }
            }
        }
        gbar(gid, tb + 4);

        // ===== F (lay0 only): XG1[t] gates 0,1 = x1[t] @ Wi1 + biases =====
        if (lay == 0) {
            // back-throttle: slot (t&7) reuses step t-8's slot
            if (tid == 0 && t >= 8) {
                unsigned tgt = (unsigned)(t - 7);
                while (ld_acq(&g_p1[oct]) < tgt) { }
            }
            __syncthreads();
            {
                const float4* xsrc = (const float4*)(g_X1 + ((size_t)t * B_ + b0g) * H_);
                for (int i = tid; i < 1024; i += NT)
                    ((float4*)scr)[i] = xsrc[i];
            }
            __syncthreads();
            {
                const int n_loc = tid & 31;            // 2 gates x 16 j
                const int ks = tid >> 5;               // 8 splits x 64 k
                const int n = (n_loc >> 4) * H_ + j0A + (n_loc & 15);
                float acc[8];
#pragma unroll
                for (int i = 0; i < 8; i++) acc[i] = 0.f;
                const float* wp = Wi1 + (size_t)(ks * 64) * G_ + n;
#pragma unroll 4
                for (int k4 = 0; k4 < 16; k4++) {
                    float w0 = wp[(size_t)(k4 * 4 + 0) * G_];
                    float w1 = wp[(size_t)(k4 * 4 + 1) * G_];
                    float w2 = wp[(size_t)(k4 * 4 + 2) * G_];
                    float w3 = wp[(size_t)(k4 * 4 + 3) * G_];
#pragma unroll
                    for (int b = 0; b < 8; b++) {
                        float4 x4 = ((const float4*)(scr + b * 512))[ks * 16 + k4];
                        acc[b] = fmaf(x4.x, w0, fmaf(x4.y, w1,
                                 fmaf(x4.z, w2, fmaf(x4.w, w3, acc[b]))));
                    }
                }
                __syncthreads();                       // staging reads done
#pragma unroll
                for (int b = 0; b < 8; b++)
                    scr[((tid >> 5) * 32 + (tid & 31)) * 8 + b] = acc[b];
                __syncthreads();
                {
                    int col = tid & 31, bb = tid >> 5;
                    float v = 0.f;
#pragma unroll
                    for (int s2 = 0; s2 < 8; s2++) v += scr[(s2 * 32 + col) * 8 + bb];
                    int g01 = col >> 4, jj = col & 15;
                    int nn = g01 * H_ + j0A + jj;
                    v += bi1[nn] + bh1[nn];
                    g_XG1[(size_t)(t & 7) * (B_ * 1024)
                          + (b0g + bb) * 1024 + g01 * 512 + j0A + jj] = v;
                }
            }
            // per-block arrival (release orders this block's F writes)
            __syncthreads();
            if (tid == 0) atom_add_acqrel(&g_p0c[oct], 1u);
        }
    }

    // reset sync state for next launch
    if (tid == 0) {
        unsigned old = atom_add_acqrel(&g_grst[gid], 1u);
        if (old == GSZ - 1) {
            g_grst[gid] = 0;
#pragma unroll
            for (int i = 0; i < 8; i++) g_bcnt[lay * B_ + b0g + i] = 0;
            if (lay == 1) { st_rel(&g_p0c[oct], 0u); st_rel(&g_p1[oct], 0u); }
            st_rel(&g_ggen[gid], 0u);
        }
    }
}

// ---------------- finalize attention output: normalize raw scores -------------
__global__ void __launch_bounds__(256) k_att(float* __restrict__ outa) {
    const int s = blockIdx.x;
    for (int i = threadIdx.x; i < T_ * B_; i += 256) {
        float v = outa[(size_t)s * (T_ * B_) + i];
        outa[(size_t)s * (T_ * B_) + i] = expf(v - g_M[i]) * g_iZ[i];
    }
}

// ---------------- host orchestration ------------------------------------------
extern "C" void kernel_launch(void* const* d_in, const int* in_sizes, int n_in,
                              void* d_out, int out_size) {
    const float* input = (const float*)d_in[0];
    const float* h0    = (const float*)d_in[1];
    const float* c0    = (const float*)d_in[2];
    const float* ctx   = (const float*)d_in[3];
    const float* Wi    = (const float*)d_in[4];
    const float* bi    = (const float*)d_in[5];
    const float* Wh    = (const float*)d_in[6];
    const float* bh    = (const float*)d_in[7];
    const float* Wain  = (const float*)d_in[8];
    const float* Waout = (const float*)d_in[9];

    float* out  = (float*)d_out;
    float* outx = out;                                   // (B,T,H)
    float* outh = out  + (size_t)B_ * T_ * H_;           // (2,B,H)
    float* outc = outh + 2 * B_ * H_;                    // (2,B,H)
    float* outa = outc + 2 * B_ * H_;                    // (S, T*B)

    const int SMEM = SMEM_FLOATS * 4;  // 99,584 B -> 2 blocks/SM
    cudaFuncSetAttribute(k_wave, cudaFuncAttributeMaxDynamicSharedMemorySize, SMEM);

    k_pre<<<dim3(G_ / 64, (T_ * B_) / 128), 256>>>(input, Wi, bi, bh);
    k_wave<<<NB, NT, SMEM>>>(ctx, Wi, bi, Wh, bh, Wain, Waout, h0, c0,
                             outx, outh, outc, outa);
    k_att<<<S_, 256>>>(outa);
}

// round 16
// speedup vs baseline: 1.4043x; 1.0123x over previous
#include <cuda_runtime.h>
#include <math.h>

#define B_ 32
#define T_ 256
#define S_ 512
#define H_ 512
#define G_ 2048   // 4*H
#define NB 128    // 8 groups x 16 blocks, 1 block per SM (uniform)
#define NT 512
#define GSZ 16
#define NGRP 8

// smem floats: [0,32768) Waout slice; [32768,40960) scr; [40960,41024) sml;
//              [41024,41536) smF
#define SCR 32768
#define SML 40960
#define SMF 41024
#define SMEM_FLOATS 41536

// ---------------- scratch: __device__ globals ---------------------------------
__device__ float g_XG[T_ * B_ * G_];       // layer0 pre-gated input (64 MB)
__device__ float g_X1[T_ * B_ * H_];       // layer0 outputs (16 MB)
__device__ float g_XG1[8 * B_ * 1024];     // lay1 gates 0,1 of XG1, 8-deep ring
__device__ float g_h[2 * B_ * H_];
__device__ float g_c[2 * B_ * H_];
__device__ float g_cat[2 * B_ * 2 * H_];   // [wc | hy]
__device__ float g_target[2 * B_ * H_];
__device__ float g_pm[2 * B_ * 2];
__device__ float g_pz[2 * B_ * 2];
__device__ float g_pwc[2 * B_ * 2 * H_];
__device__ float g_M[T_ * B_];             // layer1 softmax max
__device__ float g_iZ[T_ * B_];            // layer1 1/Z

// ---------------- sync state ---------------------------------------------------
__device__ unsigned g_gcnt[NGRP];
__device__ unsigned g_ggen[NGRP];
__device__ unsigned g_grst[NGRP];
__device__ unsigned g_bcnt[2 * B_];        // per-(layer,b) minisync (monotonic)
__device__ unsigned g_p0c[4];              // lay0 F arrivals: 16 per step
__device__ unsigned g_p1[4];               // layer1 consumption progress

__device__ __forceinline__ unsigned atom_add_acqrel(unsigned* p, unsigned v) {
    unsigned old;
    asm volatile("atom.add.acq_rel.gpu.u32 %0, [%1], %2;"
                 : "=r"(old) : "l"(p), "r"(v) : "memory");
    return old;
}
__device__ __forceinline__ unsigned ld_acq(unsigned* p) {
    unsigned v;
    asm volatile("ld.acquire.gpu.u32 %0, [%1];" : "=r"(v) : "l"(p) : "memory");
    return v;
}
__device__ __forceinline__ void st_rel(unsigned* p, unsigned v) {
    asm volatile("st.release.gpu.u32 [%0], %1;" :: "l"(p), "r"(v) : "memory");
}
__device__ __forceinline__ void gbar(int gid, unsigned target) {
    __syncthreads();
    if (threadIdx.x == 0) {
        unsigned old = atom_add_acqrel(&g_gcnt[gid], 1u);
        if (old == GSZ - 1) {
            g_gcnt[gid] = 0;
            st_rel(&g_ggen[gid], target);
        } else {
            while (ld_acq(&g_ggen[gid]) != target) { }
        }
    }
    __syncthreads();
}

// ---------------- precompute XG = x @ Wi0 + (bi0 + bh0), layer 0 only ---------
__global__ void __launch_bounds__(256) k_pre(const float* __restrict__ Xin,
                                             const float* __restrict__ Wi,
                                             const float* __restrict__ bi,
                                             const float* __restrict__ bh) {
    __shared__ float As[16][128];
    __shared__ float Bs[16][64];
    const int tid = threadIdx.x;
    const int tx = tid & 15, ty = tid >> 4;
    const int n0 = blockIdx.x * 64, m0 = blockIdx.y * 128;
    const int m_l = tid & 127, kb = (tid >> 7) * 8;
    const int m = m0 + m_l;
    const int bb = m & 31, tt = m >> 5;
    const float* arow = Xin + ((size_t)bb * T_ + tt) * H_;
    const int bkk = tid >> 4, bnn = (tid & 15) * 4;

    float acc[8][4];
#pragma unroll
    for (int i = 0; i < 8; i++)
#pragma unroll
        for (int j = 0; j < 4; j++) acc[i][j] = 0.f;

    for (int k0 = 0; k0 < H_; k0 += 16) {
        float4 a0 = *(const float4*)(arow + k0 + kb);
        float4 a1 = *(const float4*)(arow + k0 + kb + 4);
        As[kb + 0][m_l] = a0.x; As[kb + 1][m_l] = a0.y;
        As[kb + 2][m_l] = a0.z; As[kb + 3][m_l] = a0.w;
        As[kb + 4][m_l] = a1.x; As[kb + 5][m_l] = a1.y;
        As[kb + 6][m_l] = a1.z; As[kb + 7][m_l] = a1.w;
        *(float4*)&Bs[bkk][bnn] =
            *(const float4*)(Wi + (size_t)(k0 + bkk) * G_ + n0 + bnn);
        __syncthreads();
#pragma unroll
        for (int kk = 0; kk < 16; kk++) {
            float4 b4  = *(const float4*)&Bs[kk][tx * 4];
            float4 alo = *(const float4*)&As[kk][ty * 8];
            float4 ahi = *(const float4*)&As[kk][ty * 8 + 4];
            float av[8] = {alo.x, alo.y, alo.z, alo.w, ahi.x, ahi.y, ahi.z, ahi.w};
#pragma unroll
            for (int i = 0; i < 8; i++) {
                acc[i][0] = fmaf(av[i], b4.x, acc[i][0]);
                acc[i][1] = fmaf(av[i], b4.y, acc[i][1]);
                acc[i][2] = fmaf(av[i], b4.z, acc[i][2]);
                acc[i][3] = fmaf(av[i], b4.w, acc[i][3]);
            }
        }
        __syncthreads();
    }
    float4 b1 = *(const float4*)(bi + n0 + tx * 4);
    float4 b2 = *(const float4*)(bh + n0 + tx * 4);
    float4 bias = {b1.x + b2.x, b1.y + b2.y, b1.z + b2.z, b1.w + b2.w};
#pragma unroll
    for (int i = 0; i < 8; i++) {
        float4 o = {acc[i][0] + bias.x, acc[i][1] + bias.y,
                    acc[i][2] + bias.z, acc[i][3] + bias.w};
        *(float4*)&g_XG[(size_t)(m0 + ty * 8 + i) * G_ + n0 + tx * 4] = o;
    }
}

// ---------------- persistent wavefront kernel: both layers concurrently -------
__global__ void __launch_bounds__(NT, 1) k_wave(
    const float* __restrict__ ctx,
    const float* __restrict__ Wi,
    const float* __restrict__ bi,
    const float* __restrict__ Wh,
    const float* __restrict__ bh,
    const float* __restrict__ Wain,
    const float* __restrict__ Waout,
    const float* __restrict__ h0,
    const float* __restrict__ c0,
    float* __restrict__ outx,
    float* __restrict__ outh,
    float* __restrict__ outc,
    float* __restrict__ outa)
{
    extern __shared__ float sm[];
    float* smO = sm;            // Waout slice [1024k][32n], float4-over-k
    float* scr = sm + SCR;      // 8192-float stage/reduce overlay
    float* sml = sm + SML;      // 64-float small area
    float* smF = sm + SMF;      // 512-float lay1-local XG1 gates 2,3
    const int blk = blockIdx.x, tid = threadIdx.x;
    const int lane = tid & 31, wrp = tid >> 5;
    const int gid = blk >> 4, gblk = blk & 15;
    const int lay = gid >> 2, oct = gid & 3;
    const int b0g = oct * 8;

    const int bC = b0g + (gblk >> 1), qC = gblk & 1;   // phase C/D mapping
    const int j0A = gblk * 32;                         // phase A/F j-slice
    const int n0E = gblk * 32;                         // phase B/E n-slice

    // per-layer weight pointers
    const float* WiL    = Wi    + (size_t)lay * H_ * G_;
    const float* Wi1    = Wi    + (size_t)H_ * G_;
    const float* biL    = bi    + lay * G_;
    const float* bhL    = bh    + lay * G_;
    const float* bi1    = bi    + G_;
    const float* bh1    = bh    + G_;
    const float* WhL    = Wh    + (size_t)lay * H_ * G_;
    const float* WainL  = Wain  + (size_t)lay * H_ * H_;
    const float* WaoutL = Waout + (size_t)lay * 2 * H_ * H_;

    float* hL   = g_h   + lay * B_ * H_;
    float* cL   = g_c   + lay * B_ * H_;
    float* catL = g_cat + lay * B_ * 2 * H_;
    float* tgtL = g_target + lay * B_ * H_;
    float* pmL  = g_pm  + lay * B_ * 2;
    float* pzL  = g_pz  + lay * B_ * 2;
    float* pwcL = g_pwc + (size_t)lay * B_ * 2 * H_;

    // ---- one-time Waout slice preload (1024 k x 32 n) ----
    for (int idx = tid; idx < 32768; idx += NT) {
        int k = idx >> 5, nl = idx & 31;
        smO[((k >> 2) * 32 + nl) * 4 + (k & 3)] =
            WaoutL[(size_t)k * H_ + n0E + nl];
    }
    __syncthreads();

    for (int t = 0; t < T_; t++) {
        const unsigned tb = (unsigned)t * 4;

        // ===== cross-layer gate + F' (lay1: gates 2,3 of XG1 locally) =====
        if (lay == 1) {
            if (tid == 0) {
                unsigned tgt = 16u * (unsigned)(t + 1);
                while (ld_acq(&g_p0c[oct]) < tgt) { }
            }
            __syncthreads();
            {
                const float4* xsrc = (const float4*)(g_X1 + ((size_t)t * B_ + b0g) * H_);
                for (int i = tid; i < 1024; i += NT)
                    ((float4*)scr)[i] = xsrc[i];
            }
            __syncthreads();
            {
                const int n_loc = tid & 63;            // 2 gates x 32 j
                const int ks = tid >> 6;               // 8 splits x 64 k
                const int n = (2 + (n_loc >> 5)) * H_ + j0A + (n_loc & 31);
                float acc[8];
#pragma unroll
                for (int i = 0; i < 8; i++) acc[i] = 0.f;
                const float* wp = WiL + (size_t)(ks * 64) * G_ + n;
#pragma unroll 4
                for (int k4 = 0; k4 < 16; k4++) {
                    float w0 = wp[(size_t)(k4 * 4 + 0) * G_];
                    float w1 = wp[(size_t)(k4 * 4 + 1) * G_];
                    float w2 = wp[(size_t)(k4 * 4 + 2) * G_];
                    float w3 = wp[(size_t)(k4 * 4 + 3) * G_];
#pragma unroll
                    for (int b = 0; b < 8; b++) {
                        float4 x4 = ((const float4*)(scr + b * 512))[ks * 16 + k4];
                        acc[b] = fmaf(x4.x, w0, fmaf(x4.y, w1,
                                 fmaf(x4.z, w2, fmaf(x4.w, w3, acc[b]))));
                    }
                }
                __syncthreads();                       // staging reads done
#pragma unroll
                for (int b = 0; b < 8; b++)
                    scr[(ks * 64 + n_loc) * 8 + b] = acc[b];
                __syncthreads();
                {   // 512 slots: 8b x 64 col
                    int col = tid & 63, bb = tid >> 6;
                    float v = 0.f;
#pragma unroll
                    for (int s2 = 0; s2 < 8; s2++) v += scr[(s2 * 64 + col) * 8 + bb];
                    int nn = (2 + (col >> 5)) * H_ + j0A + (col & 31);
                    v += biL[nn] + bhL[nn];
                    smF[bb * 64 + col] = v;
                }
            }
            __syncthreads();
        }

        // ===== A: gates = XG + h@Wh (K=512 both layers), fused LSTM =====
        {
            const float* hp = (t == 0) ? (h0) : hL;
            for (int i = tid; i < 1024; i += NT)
                ((float4*)scr)[i] = ((const float4*)(hp + b0g * H_))[i];
            __syncthreads();
            const int n_loc = tid & 127;               // 4 gates x 32 j
            const int ks = tid >> 7;                   // 4 splits x 128 k
            const int n = (n_loc >> 5) * H_ + j0A + (n_loc & 31);
            float acc[8];
#pragma unroll
            for (int i = 0; i < 8; i++) acc[i] = 0.f;
            {
                const float* wp = WhL + (size_t)(ks * 128) * G_ + n;
                const float* hb = scr + ks * 128;
#pragma unroll 4
                for (int k4 = 0; k4 < 32; k4++) {
                    float w0 = wp[(size_t)(k4 * 4 + 0) * G_];
                    float w1 = wp[(size_t)(k4 * 4 + 1) * G_];
                    float w2 = wp[(size_t)(k4 * 4 + 2) * G_];
                    float w3 = wp[(size_t)(k4 * 4 + 3) * G_];
#pragma unroll
                    for (int b = 0; b < 8; b++) {
                        float4 h4 = ((const float4*)(hb + b * 512))[k4];
                        acc[b] = fmaf(h4.x, w0, fmaf(h4.y, w1,
                                 fmaf(h4.z, w2, fmaf(h4.w, w3, acc[b]))));
                    }
                }
            }
            __syncthreads();                           // staging reads done
#pragma unroll
            for (int b = 0; b < 8; b++) scr[(ks * 128 + n_loc) * 8 + b] = acc[b];
            __syncthreads();
            for (int slot = tid; slot < 1024; slot += NT) {
                int bb = slot >> 7, nl = slot & 127;
                int g2 = nl >> 5, j2 = nl & 31;
                float v = scr[nl * 8 + bb] + scr[(128 + nl) * 8 + bb]
                        + scr[(256 + nl) * 8 + bb] + scr[(384 + nl) * 8 + bb];
                if (lay == 0) {
                    v += g_XG[(size_t)(t * B_ + b0g + bb) * G_ + g2 * H_ + j0A + j2];
                } else {
                    if (g2 < 2)
                        v += g_XG1[(size_t)(t & 7) * (B_ * 1024)
                                   + (b0g + bb) * 1024 + g2 * 512 + j0A + j2];
                    else
                        v += smF[bb * 64 + (g2 - 2) * 32 + j2];
                }
                scr[4096 + slot] = v;
            }
            __syncthreads();
            if (tid < 256) {
                int bb = tid >> 5, j2 = tid & 31;
                float gi = scr[4096 + bb * 128 + j2];
                float gf = scr[4096 + bb * 128 + 32 + j2];
                float gg = scr[4096 + bb * 128 + 64 + j2];
                float go = scr[4096 + bb * 128 + 96 + j2];
                int b = b0g + bb, j = j0A + j2;
                float cold = (t == 0) ? c0[b * H_ + j] : cL[b * H_ + j];
                float ig = 1.f / (1.f + expf(-gi));
                float fg = 1.f / (1.f + expf(-gf));
                float g2v = tanhf(gg);
                float og = 1.f / (1.f + expf(-go));
                float cy = fg * cold + ig * g2v;
                float hy = og * tanhf(cy);
                cL[b * H_ + j] = cy;
                catL[b * 2 * H_ + H_ + j] = hy;
            }
        }
        gbar(gid, tb + 1);
        if (lay == 1 && gblk == 0 && tid == 0)
            st_rel(&g_p1[oct], (unsigned)(t + 1));

        // ===== B: target = hy @ Wa_in =====
        {
            for (int i = tid; i < 1024; i += NT) {
                int bb = i >> 7, f = i & 127;
                ((float4*)scr)[i] = ((const float4*)(catL + (b0g + bb) * 1024 + 512))[f];
            }
            __syncthreads();
            const int n_loc = tid & 31, ks = tid >> 5;  // 16 splits x 32 k
            float acc[8];
#pragma unroll
            for (int i = 0; i < 8; i++) acc[i] = 0.f;
            const float* wp = WainL + (size_t)(ks * 32) * H_ + n0E + n_loc;
            const float* hb = scr + ks * 32;
#pragma unroll
            for (int k4 = 0; k4 < 8; k4++) {
                float w0 = wp[(size_t)(k4 * 4 + 0) * H_];
                float w1 = wp[(size_t)(k4 * 4 + 1) * H_];
                float w2 = wp[(size_t)(k4 * 4 + 2) * H_];
                float w3 = wp[(size_t)(k4 * 4 + 3) * H_];
#pragma unroll
                for (int b = 0; b < 8; b++) {
                    float4 h4 = ((const float4*)(hb + b * 512))[k4];
                    acc[b] = fmaf(h4.x, w0, fmaf(h4.y, w1,
                             fmaf(h4.z, w2, fmaf(h4.w, w3, acc[b]))));
                }
            }
            __syncthreads();                           // staging reads done
#pragma unroll
            for (int b = 0; b < 8; b++) scr[(ks * 32 + n_loc) * 8 + b] = acc[b];
            __syncthreads();
            if (tid < 256) {
                int bb = tid >> 5, nn = tid & 31;
                float v = 0.f;
#pragma unroll
                for (int s2 = 0; s2 < 16; s2++) v += scr[(s2 * 32 + nn) * 8 + bb];
                tgtL[(b0g + bb) * H_ + n0E + nn] = v;
            }
        }
        gbar(gid, tb + 2);

        // ===== C: attention — online softmax, 16 s-rows per warp (16 warps) ==
        {
            const int b = bC, q = qC;
            const int sbase = q * 256;
            const float4* tp = (const float4*)(tgtL + b * H_);
            float4 tg0 = tp[lane],      tg1 = tp[32 + lane];
            float4 tg2 = tp[64 + lane], tg3 = tp[96 + lane];
            float m = -3.4e38f, z = 0.f;
            float4 a0 = {0,0,0,0}, a1 = a0, a2 = a0, a3 = a0;
#pragma unroll 4
            for (int i = 0; i < 16; i++) {
                int s = sbase + wrp * 16 + i;
                const float4* cr = (const float4*)(ctx + ((size_t)s * B_ + b) * H_);
                float4 c0v = cr[lane],      c1v = cr[32 + lane];
                float4 c2v = cr[64 + lane], c3v = cr[96 + lane];
                float p = c0v.x * tg0.x + c0v.y * tg0.y + c0v.z * tg0.z + c0v.w * tg0.w
                        + c1v.x * tg1.x + c1v.y * tg1.y + c1v.z * tg1.z + c1v.w * tg1.w
                        + c2v.x * tg2.x + c2v.y * tg2.y + c2v.z * tg2.z + c2v.w * tg2.w
                        + c3v.x * tg3.x + c3v.y * tg3.y + c3v.z * tg3.z + c3v.w * tg3.w;
#pragma unroll
                for (int o = 16; o; o >>= 1) p += __shfl_xor_sync(0xffffffffu, p, o);
                if (!lane && lay == 1)
                    outa[(size_t)s * (T_ * B_) + t * B_ + b] = p;   // raw score
                float mn = fmaxf(m, p);
                float sc = expf(m - mn);
                float e  = expf(p - mn);
                z = z * sc + e;
                a0.x = a0.x * sc + e * c0v.x; a0.y = a0.y * sc + e * c0v.y;
                a0.z = a0.z * sc + e * c0v.z; a0.w = a0.w * sc + e * c0v.w;
                a1.x = a1.x * sc + e * c1v.x; a1.y = a1.y * sc + e * c1v.y;
                a1.z = a1.z * sc + e * c1v.z; a1.w = a1.w * sc + e * c1v.w;
                a2.x = a2.x * sc + e * c2v.x; a2.y = a2.y * sc + e * c2v.y;
                a2.z = a2.z * sc + e * c2v.z; a2.w = a2.w * sc + e * c2v.w;
                a3.x = a3.x * sc + e * c3v.x; a3.y = a3.y * sc + e * c3v.y;
                a3.z = a3.z * sc + e * c3v.z; a3.w = a3.w * sc + e * c3v.w;
                m = mn;
            }
            if (!lane) { sml[wrp] = m; sml[16 + wrp] = z; }
            __syncthreads();
            if (wrp == 0) {
                float mw = (lane < 16) ? sml[lane] : -3.4e38f;
                float zw = (lane < 16) ? sml[16 + lane] : 0.f;
                float M = mw;
#pragma unroll
                for (int o = 16; o; o >>= 1)
                    M = fmaxf(M, __shfl_xor_sync(0xffffffffu, M, o));
                float cw = expf(mw - M);
                float Zb = zw * cw;
#pragma unroll
                for (int o = 16; o; o >>= 1) Zb += __shfl_xor_sync(0xffffffffu, Zb, o);
                if (lane < 16) sml[32 + lane] = cw;
                if (!lane) { pmL[b * 2 + q] = M; pzL[b * 2 + q] = Zb; }
            }
            __syncthreads();
            float cw = sml[32 + wrp];
            float4* wp4 = (float4*)(scr + wrp * 512);
            float4 s0v = {a0.x*cw, a0.y*cw, a0.z*cw, a0.w*cw};
            float4 s1v = {a1.x*cw, a1.y*cw, a1.z*cw, a1.w*cw};
            float4 s2v = {a2.x*cw, a2.y*cw, a2.z*cw, a2.w*cw};
            float4 s3v = {a3.x*cw, a3.y*cw, a3.z*cw, a3.w*cw};
            wp4[lane] = s0v; wp4[32 + lane] = s1v;
            wp4[64 + lane] = s2v; wp4[96 + lane] = s3v;
            __syncthreads();
            if (tid < 512) {
                float v = 0.f;
#pragma unroll
                for (int w2 = 0; w2 < 16; w2++) v += scr[w2 * 512 + tid];
                pwcL[((size_t)b * 2 + q) * H_ + tid] = v;
            }
            __syncthreads();
            if (tid == 0) atom_add_acqrel(&g_bcnt[lay * B_ + b], 1u);
        }

        // ===== D: wait 2 partials of (lay,b), combine -> wc =====
        {
            const int b = bC, q = qC;
            const int k0 = q * 256;
            if (tid == 0) {
                unsigned tgt = 2u * (unsigned)(t + 1);
                while (ld_acq(&g_bcnt[lay * B_ + b]) < tgt) { }
            }
            __syncthreads();
            if (wrp == 0) {
                float M2 = (lane < 2) ? pmL[b * 2 + lane] : -3.4e38f;
                float Z2 = (lane < 2) ? pzL[b * 2 + lane] : 0.f;
                float M = M2;
#pragma unroll
                for (int o = 16; o; o >>= 1)
                    M = fmaxf(M, __shfl_xor_sync(0xffffffffu, M, o));
                float cc = expf(M2 - M);
                float Z = Z2 * cc;
#pragma unroll
                for (int o = 16; o; o >>= 1) Z += __shfl_xor_sync(0xffffffffu, Z, o);
                if (lane < 2) sml[lane] = cc;
                if (!lane) {
                    sml[4] = 1.f / Z;
                    if (lay == 1) { g_M[t * B_ + b] = M; g_iZ[t * B_ + b] = 1.f / Z; }
                }
            }
            __syncthreads();
            if (tid < 256) {
                int k = k0 + tid;
                float iZ = sml[4];
                float v = sml[0] * pwcL[((size_t)b * 2 + 0) * H_ + k]
                        + sml[1] * pwcL[((size_t)b * 2 + 1) * H_ + k];
                catL[b * 2 * H_ + k] = v * iZ;
            }
        }
        gbar(gid, tb + 3);

        // ===== E: h = tanh([wc|hy] @ Wa_out) (smem weights), outputs =====
        {
            for (int i = tid; i < 2048; i += NT)
                ((float4*)scr)[i] = ((const float4*)(catL + b0g * 1024))[i];
            __syncthreads();
            const int n_loc = tid & 31, ks = tid >> 5;  // 16 splits x 64 k
            float acc[8];
#pragma unroll
            for (int i = 0; i < 8; i++) acc[i] = 0.f;
            const float4* w4p = (const float4*)smO + n_loc;
#pragma unroll 4
            for (int k4 = 0; k4 < 16; k4++) {
                float4 w4 = w4p[(ks * 16 + k4) * 32];
#pragma unroll
                for (int b = 0; b < 8; b++) {
                    float4 h4 = ((const float4*)(scr + b * 1024))[ks * 16 + k4];
                    acc[b] = fmaf(h4.x, w4.x, fmaf(h4.y, w4.y,
                             fmaf(h4.z, w4.z, fmaf(h4.w, w4.w, acc[b]))));
                }
            }
            __syncthreads();                           // staging reads done
#pragma unroll
            for (int b = 0; b < 8; b++) scr[(ks * 32 + n_loc) * 8 + b] = acc[b];
            __syncthreads();
            if (tid < 256) {
                int bb = tid >> 5, nn = tid & 31;
                float v = 0.f;
#pragma unroll
                for (int s2 = 0; s2 < 16; s2++) v += scr[(s2 * 32 + nn) * 8 + bb];
                v = tanhf(v);
                int b = b0g + bb, n = n0E + nn;
                hL[b * H_ + n] = v;
                if (lay == 0)
                    g_X1[((size_t)t * B_ + b) * H_ + n] = v;
                else
                    outx[(size_t)b * (T_ * H_) + (size_t)t * H_ + n] = v;
                if (t == T_ - 1) {
                    outh[lay * B_ * H_ + b * H_ + n] = v;
                    outc[lay * B_ * H_ + b * H_ + n] = cL[b * H_ + n];
                }
            }
        }
        gbar(gid, tb + 4);

        // ===== F (lay0 only): XG1[t] gates 0,1 = x1[t] @ Wi1 + biases =====
        if (lay == 0) {
            if (tid == 0 && t >= 8) {
                unsigned tgt = (unsigned)(t - 7);
                while (ld_acq(&g_p1[oct]) < tgt) { }
            }
            __syncthreads();
            {
                const float4* xsrc = (const float4*)(g_X1 + ((size_t)t * B_ + b0g) * H_);
                for (int i = tid; i < 1024; i += NT)
                    ((float4*)scr)[i] = xsrc[i];
            }
            __syncthreads();
            {
                const int n_loc = tid & 63;            // 2 gates x 32 j
                const int ks = tid >> 6;               // 8 splits x 64 k
                const int n = (n_loc >> 5) * H_ + j0A + (n_loc & 31);
                float acc[8];
#pragma unroll
                for (int i = 0; i < 8; i++) acc[i] = 0.f;
                const float* wp = Wi1 + (size_t)(ks * 64) * G_ + n;
#pragma unroll 4
                for (int k4 = 0; k4 < 16; k4++) {
                    float w0 = wp[(size_t)(k4 * 4 + 0) * G_];
                    float w1 = wp[(size_t)(k4 * 4 + 1) * G_];
                    float w2 = wp[(size_t)(k4 * 4 + 2) * G_];
                    float w3 = wp[(size_t)(k4 * 4 + 3) * G_];
#pragma unroll
                    for (int b = 0; b < 8; b++) {
                        float4 x4 = ((const float4*)(scr + b * 512))[ks * 16 + k4];
                        acc[b] = fmaf(x4.x, w0, fmaf(x4.y, w1,
                                 fmaf(x4.z, w2, fmaf(x4.w, w3, acc[b]))));
                    }
                }
                __syncthreads();                       // staging reads done
#pragma unroll
                for (int b = 0; b < 8; b++)
                    scr[(ks * 64 + n_loc) * 8 + b] = acc[b];
                __syncthreads();
                {
                    int col = tid & 63, bb = tid >> 6;
                    float v = 0.f;
#pragma unroll
                    for (int s2 = 0; s2 < 8; s2++) v += scr[(s2 * 64 + col) * 8 + bb];
                    int g01 = col >> 5, jj = col & 31;
                    int nn = g01 * H_ + j0A + jj;
                    v += bi1[nn] + bh1[nn];
                    g_XG1[(size_t)(t & 7) * (B_ * 1024)
                          + (b0g + bb) * 1024 + g01 * 512 + j0A + jj] = v;
                }
            }
            __syncthreads();
            if (tid == 0) atom_add_acqrel(&g_p0c[oct], 1u);
        }
    }

    // reset sync state for next launch
    if (tid == 0) {
        unsigned old = atom_add_acqrel(&g_grst[gid], 1u);
        if (old == GSZ - 1) {
            g_grst[gid] = 0;
#pragma unroll
            for (int i = 0; i < 8; i++) g_bcnt[lay * B_ + b0g + i] = 0;
            if (lay == 1) { st_rel(&g_p0c[oct], 0u); st_rel(&g_p1[oct], 0u); }
            st_rel(&g_ggen[gid], 0u);
        }
    }
}

// ---------------- finalize attention output: normalize raw scores -------------
__global__ void __launch_bounds__(256) k_att(float* __restrict__ outa) {
    const int s = blockIdx.x;
    for (int i = threadIdx.x; i < T_ * B_; i += 256) {
        float v = outa[(size_t)s * (T_ * B_) + i];
        outa[(size_t)s * (T_ * B_) + i] = expf(v - g_M[i]) * g_iZ[i];
    }
}

// ---------------- host orchestration ------------------------------------------
extern "C" void kernel_launch(void* const* d_in, const int* in_sizes, int n_in,
                              void* d_out, int out_size) {
    const float* input = (const float*)d_in[0];
    const float* h0    = (const float*)d_in[1];
    const float* c0    = (const float*)d_in[2];
    const float* ctx   = (const float*)d_in[3];
    const float* Wi    = (const float*)d_in[4];
    const float* bi    = (const float*)d_in[5];
    const float* Wh    = (const float*)d_in[6];
    const float* bh    = (const float*)d_in[7];
    const float* Wain  = (const float*)d_in[8];
    const float* Waout = (const float*)d_in[9];

    float* out  = (float*)d_out;
    float* outx = out;                                   // (B,T,H)
    float* outh = out  + (size_t)B_ * T_ * H_;           // (2,B,H)
    float* outc = outh + 2 * B_ * H_;                    // (2,B,H)
    float* outa = outc + 2 * B_ * H_;                    // (S, T*B)

    const int SMEM = SMEM_FLOATS * 4;  // 166,144 B -> 1 block/SM
    cudaFuncSetAttribute(k_wave, cudaFuncAttributeMaxDynamicSharedMemorySize, SMEM);

    k_pre<<<dim3(G_ / 64, (T_ * B_) / 128), 256>>>(input, Wi, bi, bh);
    k_wave<<<NB, NT, SMEM>>>(ctx, Wi, bi, Wh, bh, Wain, Waout, h0, c0,
                             outx, outh, outc, outa);
    k_att<<<S_, 256>>>(outa);
}